// round 1
// baseline (speedup 1.0000x reference)
#include <cuda_runtime.h>
#include <math.h>

// Problem dims
#define NBATCH 16
#define SEQ    2048
#define EMB    256
#define NROWS  (NBATCH*SEQ)   // 32768
#define NQD    8
#define FFND   512

// scratch: activations [NROWS, EMB] fp32
__device__ float g_x[NROWS*EMB];
__device__ float g_freq[128];

__device__ __forceinline__ float2 ffma2(float2 a, float2 b, float2 c){
    float2 d;
    asm("fma.rn.f32x2 %0, %1, %2, %3;"
        : "=l"(reinterpret_cast<unsigned long long&>(d))
        : "l"(reinterpret_cast<unsigned long long&>(a)),
          "l"(reinterpret_cast<unsigned long long&>(b)),
          "l"(reinterpret_cast<unsigned long long&>(c)));
    return d;
}

// ---------------------------------------------------------------------------
// freq table for positional encoding (double precision -> correctly rounded f32)
__global__ void k_freq(){
    int i = threadIdx.x;
    if (i < 128)
        g_freq[i] = (float)exp(-(double)(2*i) * (log(10000.0) / 256.0));
}

// ---------------------------------------------------------------------------
// x = embed[tokens] + pos_encoding
__global__ void k_embed(const int* __restrict__ tokens,
                        const float* __restrict__ embed){
    int row = blockIdx.x;          // b*SEQ + s
    int e   = threadIdx.x;         // 0..255
    int tok = tokens[row];
    float v = embed[tok*EMB + e];
    float freq = g_freq[e >> 1];
    float ang  = (float)(row & (SEQ-1)) * freq;
    v += (e & 1) ? cosf(ang) : sinf(ang);
    g_x[row*EMB + e] = v;
}

// ---------------------------------------------------------------------------
// Fused: attn = cos(x+theta) @ W + b ; x = LN(x + attn)
// 64 rows per block, 256 threads. A transposed in smem for float2 row-pair loads.
#define AS_STRIDE 66
#define SMEM_A ((256*AS_STRIDE + 32*256) * 4)   // 100352 bytes

__global__ __launch_bounds__(256, 2) void k_attn(
    const float* __restrict__ theta,   // [64]
    const float* __restrict__ W,       // [256,256] row-major (e,f)
    const float* __restrict__ cbias,   // [256]
    const float* __restrict__ lng,
    const float* __restrict__ lnb)
{
    extern __shared__ float sm[];
    float* Acos = sm;                      // [256][AS_STRIDE] (k-major, transposed)
    float* Bs   = sm + 256*AS_STRIDE;      // [32][256]

    int tid   = threadIdx.x;
    int row0  = blockIdx.x * 64;
    int c0    = tid & 63;
    int rbase = (tid >> 6) * 16;

    // fill Acos: thread owns column k = tid, walks 64 rows (gmem coalesced)
    {
        float th = theta[tid & 63];
        const float* xp = g_x + row0*EMB + tid;
        #pragma unroll
        for (int r = 0; r < 64; r++)
            Acos[tid*AS_STRIDE + r] = cosf(xp[r*EMB] + th);
    }

    float2 acc[8][4];
    #pragma unroll
    for (int p=0;p<8;p++)
        #pragma unroll
        for (int j=0;j<4;j++) acc[p][j] = make_float2(0.f, 0.f);

    for (int k0 = 0; k0 < 256; k0 += 32){
        // stage B chunk (contiguous 8192 floats) as float4
        {
            const float4* Wv = reinterpret_cast<const float4*>(W + k0*256);
            float4* Bv4 = reinterpret_cast<float4*>(Bs);
            #pragma unroll
            for (int i = 0; i < 8; i++) Bv4[tid + 256*i] = Wv[tid + 256*i];
        }
        __syncthreads();
        #pragma unroll
        for (int kk = 0; kk < 32; kk++){
            float2 a[8];
            #pragma unroll
            for (int p=0;p<8;p++)
                a[p] = *reinterpret_cast<const float2*>(&Acos[(k0+kk)*AS_STRIDE + rbase + 2*p]);
            float b[4];
            #pragma unroll
            for (int j=0;j<4;j++) b[j] = Bs[kk*256 + c0 + 64*j];
            #pragma unroll
            for (int p=0;p<8;p++)
                #pragma unroll
                for (int j=0;j<4;j++)
                    acc[p][j] = ffma2(a[p], make_float2(b[j], b[j]), acc[p][j]);
        }
        __syncthreads();
    }

    // z = acc + bias + x  -> staged into smem (reuse Acos region)
    float* zbuf = sm;   // [64][256]
    float bj[4];
    #pragma unroll
    for (int j=0;j<4;j++) bj[j] = cbias[c0 + 64*j];
    #pragma unroll
    for (int p=0;p<8;p++){
        #pragma unroll
        for (int h=0;h<2;h++){
            int r = rbase + 2*p + h;
            const float* xr = g_x + (row0+r)*EMB;
            #pragma unroll
            for (int j=0;j<4;j++){
                float av = h ? acc[p][j].y : acc[p][j].x;
                zbuf[r*256 + c0 + 64*j] = av + bj[j] + xr[c0 + 64*j];
            }
        }
    }
    __syncthreads();

    // LayerNorm: 8 warps x 8 rows
    int warp = tid >> 5, lane = tid & 31;
    float gv[8], bv[8];
    #pragma unroll
    for (int u=0;u<8;u++){ gv[u] = lng[lane+32*u]; bv[u] = lnb[lane+32*u]; }
    for (int rr = 0; rr < 8; rr++){
        int r = warp*8 + rr;
        float v[8], s = 0.f, q = 0.f;
        #pragma unroll
        for (int u=0;u<8;u++){ v[u] = zbuf[r*256 + lane + 32*u]; s += v[u]; q += v[u]*v[u]; }
        #pragma unroll
        for (int off=16; off; off>>=1){
            s += __shfl_xor_sync(0xffffffffu, s, off);
            q += __shfl_xor_sync(0xffffffffu, q, off);
        }
        float m   = s * (1.f/256.f);
        float var = fmaxf(q * (1.f/256.f) - m*m, 0.f);
        float rs  = rsqrtf(var + 1e-5f);
        float* xo = g_x + (row0+r)*EMB;
        #pragma unroll
        for (int u=0;u<8;u++) xo[lane+32*u] = (v[u]-m)*rs*gv[u] + bv[u];
    }
}

// ---------------------------------------------------------------------------
// Fused FFN: q = cos(x[:,:8])*cos(ftheta); h = relu(q@W1+b1) (32-wide f chunks);
// ffn = h@W2 + b2; x = LN(x + ffn)
#define HS_STRIDE 66
// floats: Xs 16384 + Hs 32*66 + Bs 8192 + W1s 256 + Qs 512 = 27456
#define SMEM_B (27456 * 4)   // 109824 bytes

__global__ __launch_bounds__(256, 2) void k_ffn(
    const float* __restrict__ ftheta,  // [8]
    const float* __restrict__ W1,      // [8,512]
    const float* __restrict__ b1,      // [512]
    const float* __restrict__ W2,      // [512,256]
    const float* __restrict__ b2,      // [256]
    const float* __restrict__ lng,
    const float* __restrict__ lnb)
{
    extern __shared__ float sm[];
    float* Xs  = sm;                       // [64][256]
    float* Hs  = sm + 16384;               // [32][HS_STRIDE] transposed
    float* Bs  = Hs + 32*HS_STRIDE;        // [32][256]
    float* W1s = Bs + 8192;                // [8][32]
    float* Qs  = W1s + 256;                // [64][8]

    int tid   = threadIdx.x;
    int row0  = blockIdx.x * 64;
    int c0    = tid & 63;
    int rbase = (tid >> 6) * 16;

    // load x rows
    {
        const float* xp = g_x + row0*EMB + tid;
        #pragma unroll
        for (int r = 0; r < 64; r++) Xs[r*256 + tid] = xp[r*EMB];
    }
    __syncthreads();

    // q[r][n] = cos(x[r][n]) * cos(ftheta[n])
    for (int i = tid; i < 64*NQD; i += 256){
        int r = i >> 3, n = i & 7;
        Qs[i] = cosf(Xs[r*256 + n]) * cosf(ftheta[n]);
    }

    float2 acc[8][4];
    #pragma unroll
    for (int p=0;p<8;p++)
        #pragma unroll
        for (int j=0;j<4;j++) acc[p][j] = make_float2(0.f, 0.f);

    for (int f0 = 0; f0 < FFND; f0 += 32){
        // stage W1 chunk [8][32] and W2 chunk [32][256]
        { int n = tid >> 5, fi = tid & 31;
          W1s[tid] = W1[n*FFND + f0 + fi]; }
        {
            const float4* Wv = reinterpret_cast<const float4*>(W2 + f0*256);
            float4* Bv4 = reinterpret_cast<float4*>(Bs);
            #pragma unroll
            for (int i = 0; i < 8; i++) Bv4[tid + 256*i] = Wv[tid + 256*i];
        }
        __syncthreads();

        // h chunk [64 rows][32 f] -> transposed smem
        #pragma unroll
        for (int i = 0; i < 8; i++){
            int id = tid + 256*i;
            int fi = id & 31, r = id >> 5;
            float h = b1[f0 + fi];
            #pragma unroll
            for (int n = 0; n < NQD; n++) h += Qs[r*8 + n] * W1s[n*32 + fi];
            Hs[fi*HS_STRIDE + r] = fmaxf(h, 0.f);
        }
        __syncthreads();

        #pragma unroll
        for (int kk = 0; kk < 32; kk++){
            float2 a[8];
            #pragma unroll
            for (int p=0;p<8;p++)
                a[p] = *reinterpret_cast<const float2*>(&Hs[kk*HS_STRIDE + rbase + 2*p]);
            float b[4];
            #pragma unroll
            for (int j=0;j<4;j++) b[j] = Bs[kk*256 + c0 + 64*j];
            #pragma unroll
            for (int p=0;p<8;p++)
                #pragma unroll
                for (int j=0;j<4;j++)
                    acc[p][j] = ffma2(a[p], make_float2(b[j], b[j]), acc[p][j]);
        }
        __syncthreads();
    }

    // residual + bias into Xs in-place (each address owned by exactly one thread)
    float bj[4];
    #pragma unroll
    for (int j=0;j<4;j++) bj[j] = b2[c0 + 64*j];
    #pragma unroll
    for (int p=0;p<8;p++){
        #pragma unroll
        for (int h=0;h<2;h++){
            int r = rbase + 2*p + h;
            #pragma unroll
            for (int j=0;j<4;j++){
                float av = h ? acc[p][j].y : acc[p][j].x;
                int idx = r*256 + c0 + 64*j;
                Xs[idx] = av + bj[j] + Xs[idx];
            }
        }
    }
    __syncthreads();

    // LayerNorm
    int warp = tid >> 5, lane = tid & 31;
    float gv[8], bv[8];
    #pragma unroll
    for (int u=0;u<8;u++){ gv[u] = lng[lane+32*u]; bv[u] = lnb[lane+32*u]; }
    for (int rr = 0; rr < 8; rr++){
        int r = warp*8 + rr;
        float v[8], s = 0.f, q = 0.f;
        #pragma unroll
        for (int u=0;u<8;u++){ v[u] = Xs[r*256 + lane + 32*u]; s += v[u]; q += v[u]*v[u]; }
        #pragma unroll
        for (int off=16; off; off>>=1){
            s += __shfl_xor_sync(0xffffffffu, s, off);
            q += __shfl_xor_sync(0xffffffffu, q, off);
        }
        float m   = s * (1.f/256.f);
        float var = fmaxf(q * (1.f/256.f) - m*m, 0.f);
        float rs  = rsqrtf(var + 1e-5f);
        float* xo = g_x + (row0+r)*EMB;
        #pragma unroll
        for (int u=0;u<8;u++) xo[lane+32*u] = (v[u]-m)*rs*gv[u] + bv[u];
    }
}

// ---------------------------------------------------------------------------
// pooled = mean_s(x);  out = pooled @ cls_w + cls_b
__global__ void k_cls(const float* __restrict__ cw,
                      const float* __restrict__ cb,
                      float* __restrict__ out){
    int b = blockIdx.x, tid = threadIdx.x;
    const float* xp = g_x + b*SEQ*EMB + tid;
    float s = 0.f;
    for (int i = 0; i < SEQ; i++) s += xp[i*EMB];
    float p  = s * (1.f/(float)SEQ);
    float l0 = p * cw[tid*2 + 0];
    float l1 = p * cw[tid*2 + 1];
    #pragma unroll
    for (int off=16; off; off>>=1){
        l0 += __shfl_xor_sync(0xffffffffu, l0, off);
        l1 += __shfl_xor_sync(0xffffffffu, l1, off);
    }
    __shared__ float r0[8], r1[8];
    int warp = tid >> 5, lane = tid & 31;
    if (lane == 0){ r0[warp] = l0; r1[warp] = l1; }
    __syncthreads();
    if (tid == 0){
        float a = cb[0], c = cb[1];
        #pragma unroll
        for (int w = 0; w < 8; w++){ a += r0[w]; c += r1[w]; }
        out[b*2 + 0] = a;
        out[b*2 + 1] = c;
    }
}

// ---------------------------------------------------------------------------
extern "C" void kernel_launch(void* const* d_in, const int* in_sizes, int n_in,
                              void* d_out, int out_size){
    const int*   tokens      = (const int*)  d_in[0];
    const float* embed       = (const float*)d_in[1];
    const float* attn_theta  = (const float*)d_in[2];   // [2,64]
    const float* combine_w   = (const float*)d_in[3];   // [2,256,256]
    const float* combine_b   = (const float*)d_in[4];   // [2,256]
    const float* ffn_theta   = (const float*)d_in[5];   // [2,8]
    const float* lin1_w      = (const float*)d_in[6];   // [2,8,512]
    const float* lin1_b      = (const float*)d_in[7];   // [2,512]
    const float* lin2_w      = (const float*)d_in[8];   // [2,512,256]
    const float* lin2_b      = (const float*)d_in[9];   // [2,256]
    const float* ln1_g       = (const float*)d_in[10];
    const float* ln1_b       = (const float*)d_in[11];
    const float* ln2_g       = (const float*)d_in[12];
    const float* ln2_b       = (const float*)d_in[13];
    const float* cls_w       = (const float*)d_in[14];  // [256,2]
    const float* cls_b       = (const float*)d_in[15];  // [2]
    float* out = (float*)d_out;

    cudaFuncSetAttribute(k_attn, cudaFuncAttributeMaxDynamicSharedMemorySize, SMEM_A);
    cudaFuncSetAttribute(k_ffn,  cudaFuncAttributeMaxDynamicSharedMemorySize, SMEM_B);

    k_freq<<<1, 128>>>();
    k_embed<<<NROWS, 256>>>(tokens, embed);
    for (int l = 0; l < 2; l++){
        k_attn<<<NROWS/64, 256, SMEM_A>>>(attn_theta + l*64,
                                          combine_w + l*256*256,
                                          combine_b + l*256,
                                          ln1_g + l*256, ln1_b + l*256);
        k_ffn<<<NROWS/64, 256, SMEM_B>>>(ffn_theta + l*8,
                                         lin1_w + l*8*512,
                                         lin1_b + l*512,
                                         lin2_w + l*512*256,
                                         lin2_b + l*256,
                                         ln2_g + l*256, ln2_b + l*256);
    }
    k_cls<<<NBATCH, 256>>>(cls_w, cls_b, out);
}

// round 2
// speedup vs baseline: 1.0037x; 1.0037x over previous
#include <cuda_runtime.h>
#include <math.h>

// Problem dims
#define NBATCH 16
#define SEQ    2048
#define EMB    256
#define NROWS  (NBATCH*SEQ)   // 32768
#define NQD    8
#define FFND   512

// scratch: activations [NROWS, EMB] fp32
__device__ float g_x[NROWS*EMB];
__device__ float g_freq[128];

__device__ __forceinline__ float2 ffma2(float2 a, float2 b, float2 c){
    float2 d;
    asm("fma.rn.f32x2 %0, %1, %2, %3;"
        : "=l"(reinterpret_cast<unsigned long long&>(d))
        : "l"(reinterpret_cast<unsigned long long&>(a)),
          "l"(reinterpret_cast<unsigned long long&>(b)),
          "l"(reinterpret_cast<unsigned long long&>(c)));
    return d;
}

// ---------------------------------------------------------------------------
// freq table for positional encoding (double precision -> correctly rounded f32)
__global__ void k_freq(){
    int i = threadIdx.x;
    if (i < 128)
        g_freq[i] = (float)exp(-(double)(2*i) * (log(10000.0) / 256.0));
}

// ---------------------------------------------------------------------------
// x = embed[tokens] + pos_encoding
__global__ void k_embed(const int* __restrict__ tokens,
                        const float* __restrict__ embed){
    int row = blockIdx.x;          // b*SEQ + s
    int e   = threadIdx.x;         // 0..255
    int tok = tokens[row];
    float v = embed[tok*EMB + e];
    float freq = g_freq[e >> 1];
    float ang  = (float)(row & (SEQ-1)) * freq;
    v += (e & 1) ? cosf(ang) : sinf(ang);
    g_x[row*EMB + e] = v;
}

// ---------------------------------------------------------------------------
// Fused: attn = cos(x+theta) @ W + b ; x = LN(x + attn)
// 64 rows per block, 256 threads. A transposed in smem for float2 row-pair loads.
#define AS_STRIDE 66
#define SMEM_A ((256*AS_STRIDE + 32*256) * 4)   // 100352 bytes

__global__ __launch_bounds__(256, 2) void k_attn(
    const float* __restrict__ theta,   // [64]
    const float* __restrict__ W,       // [256,256] row-major (e,f)
    const float* __restrict__ cbias,   // [256]
    const float* __restrict__ lng,
    const float* __restrict__ lnb)
{
    extern __shared__ float sm[];
    float* Acos = sm;                      // [256][AS_STRIDE] (k-major, transposed)
    float* Bs   = sm + 256*AS_STRIDE;      // [32][256]

    int tid   = threadIdx.x;
    int row0  = blockIdx.x * 64;
    int c0    = tid & 63;
    int rbase = (tid >> 6) * 16;

    // fill Acos: thread owns column k = tid, walks 64 rows (gmem coalesced)
    {
        float th = theta[tid & 63];
        const float* xp = g_x + row0*EMB + tid;
        #pragma unroll
        for (int r = 0; r < 64; r++)
            Acos[tid*AS_STRIDE + r] = cosf(xp[r*EMB] + th);
    }

    float2 acc[8][4];
    #pragma unroll
    for (int p=0;p<8;p++)
        #pragma unroll
        for (int j=0;j<4;j++) acc[p][j] = make_float2(0.f, 0.f);

    for (int k0 = 0; k0 < 256; k0 += 32){
        // stage B chunk (contiguous 8192 floats) as float4
        {
            const float4* Wv = reinterpret_cast<const float4*>(W + k0*256);
            float4* Bv4 = reinterpret_cast<float4*>(Bs);
            #pragma unroll
            for (int i = 0; i < 8; i++) Bv4[tid + 256*i] = Wv[tid + 256*i];
        }
        __syncthreads();
        #pragma unroll
        for (int kk = 0; kk < 32; kk++){
            float2 a[8];
            #pragma unroll
            for (int p=0;p<8;p++)
                a[p] = *reinterpret_cast<const float2*>(&Acos[(k0+kk)*AS_STRIDE + rbase + 2*p]);
            float b[4];
            #pragma unroll
            for (int j=0;j<4;j++) b[j] = Bs[kk*256 + c0 + 64*j];
            #pragma unroll
            for (int p=0;p<8;p++)
                #pragma unroll
                for (int j=0;j<4;j++)
                    acc[p][j] = ffma2(a[p], make_float2(b[j], b[j]), acc[p][j]);
        }
        __syncthreads();
    }

    // z = acc + bias + x  -> staged into smem (reuse Acos region)
    float* zbuf = sm;   // [64][256]
    float bj[4];
    #pragma unroll
    for (int j=0;j<4;j++) bj[j] = cbias[c0 + 64*j];
    #pragma unroll
    for (int p=0;p<8;p++){
        #pragma unroll
        for (int h=0;h<2;h++){
            int r = rbase + 2*p + h;
            const float* xr = g_x + (row0+r)*EMB;
            #pragma unroll
            for (int j=0;j<4;j++){
                float av = h ? acc[p][j].y : acc[p][j].x;
                zbuf[r*256 + c0 + 64*j] = av + bj[j] + xr[c0 + 64*j];
            }
        }
    }
    __syncthreads();

    // LayerNorm: 8 warps x 8 rows
    int warp = tid >> 5, lane = tid & 31;
    float gv[8], bv[8];
    #pragma unroll
    for (int u=0;u<8;u++){ gv[u] = lng[lane+32*u]; bv[u] = lnb[lane+32*u]; }
    for (int rr = 0; rr < 8; rr++){
        int r = warp*8 + rr;
        float v[8], s = 0.f, q = 0.f;
        #pragma unroll
        for (int u=0;u<8;u++){ v[u] = zbuf[r*256 + lane + 32*u]; s += v[u]; q += v[u]*v[u]; }
        #pragma unroll
        for (int off=16; off; off>>=1){
            s += __shfl_xor_sync(0xffffffffu, s, off);
            q += __shfl_xor_sync(0xffffffffu, q, off);
        }
        float m   = s * (1.f/256.f);
        float var = fmaxf(q * (1.f/256.f) - m*m, 0.f);
        float rs  = rsqrtf(var + 1e-5f);
        float* xo = g_x + (row0+r)*EMB;
        #pragma unroll
        for (int u=0;u<8;u++) xo[lane+32*u] = (v[u]-m)*rs*gv[u] + bv[u];
    }
}

// ---------------------------------------------------------------------------
// Fused FFN: q = cos(x[:,:8])*cos(ftheta); h = relu(q@W1+b1) (32-wide f chunks);
// ffn = h@W2 + b2; x = LN(x + ffn)
#define HS_STRIDE 66
// floats: Xs 16384 + Hs 32*66 + Bs 8192 + W1s 256 + Qs 512 = 27456
#define SMEM_B (27456 * 4)   // 109824 bytes

__global__ __launch_bounds__(256, 2) void k_ffn(
    const float* __restrict__ ftheta,  // [8]
    const float* __restrict__ W1,      // [8,512]
    const float* __restrict__ b1,      // [512]
    const float* __restrict__ W2,      // [512,256]
    const float* __restrict__ b2,      // [256]
    const float* __restrict__ lng,
    const float* __restrict__ lnb)
{
    extern __shared__ float sm[];
    float* Xs  = sm;                       // [64][256]
    float* Hs  = sm + 16384;               // [32][HS_STRIDE] transposed
    float* Bs  = Hs + 32*HS_STRIDE;        // [32][256]
    float* W1s = Bs + 8192;                // [8][32]
    float* Qs  = W1s + 256;                // [64][8]

    int tid   = threadIdx.x;
    int row0  = blockIdx.x * 64;
    int c0    = tid & 63;
    int rbase = (tid >> 6) * 16;

    // load x rows
    {
        const float* xp = g_x + row0*EMB + tid;
        #pragma unroll
        for (int r = 0; r < 64; r++) Xs[r*256 + tid] = xp[r*EMB];
    }
    __syncthreads();

    // q[r][n] = cos(x[r][n]) * cos(ftheta[n])
    for (int i = tid; i < 64*NQD; i += 256){
        int r = i >> 3, n = i & 7;
        Qs[i] = cosf(Xs[r*256 + n]) * cosf(ftheta[n]);
    }

    float2 acc[8][4];
    #pragma unroll
    for (int p=0;p<8;p++)
        #pragma unroll
        for (int j=0;j<4;j++) acc[p][j] = make_float2(0.f, 0.f);

    for (int f0 = 0; f0 < FFND; f0 += 32){
        // stage W1 chunk [8][32] and W2 chunk [32][256]
        { int n = tid >> 5, fi = tid & 31;
          W1s[tid] = W1[n*FFND + f0 + fi]; }
        {
            const float4* Wv = reinterpret_cast<const float4*>(W2 + f0*256);
            float4* Bv4 = reinterpret_cast<float4*>(Bs);
            #pragma unroll
            for (int i = 0; i < 8; i++) Bv4[tid + 256*i] = Wv[tid + 256*i];
        }
        __syncthreads();

        // h chunk [64 rows][32 f] -> transposed smem
        #pragma unroll
        for (int i = 0; i < 8; i++){
            int id = tid + 256*i;
            int fi = id & 31, r = id >> 5;
            float h = b1[f0 + fi];
            #pragma unroll
            for (int n = 0; n < NQD; n++) h += Qs[r*8 + n] * W1s[n*32 + fi];
            Hs[fi*HS_STRIDE + r] = fmaxf(h, 0.f);
        }
        __syncthreads();

        #pragma unroll
        for (int kk = 0; kk < 32; kk++){
            float2 a[8];
            #pragma unroll
            for (int p=0;p<8;p++)
                a[p] = *reinterpret_cast<const float2*>(&Hs[kk*HS_STRIDE + rbase + 2*p]);
            float b[4];
            #pragma unroll
            for (int j=0;j<4;j++) b[j] = Bs[kk*256 + c0 + 64*j];
            #pragma unroll
            for (int p=0;p<8;p++)
                #pragma unroll
                for (int j=0;j<4;j++)
                    acc[p][j] = ffma2(a[p], make_float2(b[j], b[j]), acc[p][j]);
        }
        __syncthreads();
    }

    // residual + bias into Xs in-place (each address owned by exactly one thread)
    float bj[4];
    #pragma unroll
    for (int j=0;j<4;j++) bj[j] = b2[c0 + 64*j];
    #pragma unroll
    for (int p=0;p<8;p++){
        #pragma unroll
        for (int h=0;h<2;h++){
            int r = rbase + 2*p + h;
            #pragma unroll
            for (int j=0;j<4;j++){
                float av = h ? acc[p][j].y : acc[p][j].x;
                int idx = r*256 + c0 + 64*j;
                Xs[idx] = av + bj[j] + Xs[idx];
            }
        }
    }
    __syncthreads();

    // LayerNorm
    int warp = tid >> 5, lane = tid & 31;
    float gv[8], bv[8];
    #pragma unroll
    for (int u=0;u<8;u++){ gv[u] = lng[lane+32*u]; bv[u] = lnb[lane+32*u]; }
    for (int rr = 0; rr < 8; rr++){
        int r = warp*8 + rr;
        float v[8], s = 0.f, q = 0.f;
        #pragma unroll
        for (int u=0;u<8;u++){ v[u] = Xs[r*256 + lane + 32*u]; s += v[u]; q += v[u]*v[u]; }
        #pragma unroll
        for (int off=16; off; off>>=1){
            s += __shfl_xor_sync(0xffffffffu, s, off);
            q += __shfl_xor_sync(0xffffffffu, q, off);
        }
        float m   = s * (1.f/256.f);
        float var = fmaxf(q * (1.f/256.f) - m*m, 0.f);
        float rs  = rsqrtf(var + 1e-5f);
        float* xo = g_x + (row0+r)*EMB;
        #pragma unroll
        for (int u=0;u<8;u++) xo[lane+32*u] = (v[u]-m)*rs*gv[u] + bv[u];
    }
}

// ---------------------------------------------------------------------------
// pooled = mean_s(x);  out = pooled @ cls_w + cls_b
__global__ void k_cls(const float* __restrict__ cw,
                      const float* __restrict__ cb,
                      float* __restrict__ out){
    int b = blockIdx.x, tid = threadIdx.x;
    const float* xp = g_x + b*SEQ*EMB + tid;
    float s = 0.f;
    for (int i = 0; i < SEQ; i++) s += xp[i*EMB];
    float p  = s * (1.f/(float)SEQ);
    float l0 = p * cw[tid*2 + 0];
    float l1 = p * cw[tid*2 + 1];
    #pragma unroll
    for (int off=16; off; off>>=1){
        l0 += __shfl_xor_sync(0xffffffffu, l0, off);
        l1 += __shfl_xor_sync(0xffffffffu, l1, off);
    }
    __shared__ float r0[8], r1[8];
    int warp = tid >> 5, lane = tid & 31;
    if (lane == 0){ r0[warp] = l0; r1[warp] = l1; }
    __syncthreads();
    if (tid == 0){
        float a = cb[0], c = cb[1];
        #pragma unroll
        for (int w = 0; w < 8; w++){ a += r0[w]; c += r1[w]; }
        out[b*2 + 0] = a;
        out[b*2 + 1] = c;
    }
}

// ---------------------------------------------------------------------------
extern "C" void kernel_launch(void* const* d_in, const int* in_sizes, int n_in,
                              void* d_out, int out_size){
    const int*   tokens      = (const int*)  d_in[0];
    const float* embed       = (const float*)d_in[1];
    const float* attn_theta  = (const float*)d_in[2];   // [2,64]
    const float* combine_w   = (const float*)d_in[3];   // [2,256,256]
    const float* combine_b   = (const float*)d_in[4];   // [2,256]
    const float* ffn_theta   = (const float*)d_in[5];   // [2,8]
    const float* lin1_w      = (const float*)d_in[6];   // [2,8,512]
    const float* lin1_b      = (const float*)d_in[7];   // [2,512]
    const float* lin2_w      = (const float*)d_in[8];   // [2,512,256]
    const float* lin2_b      = (const float*)d_in[9];   // [2,256]
    const float* ln1_g       = (const float*)d_in[10];
    const float* ln1_b       = (const float*)d_in[11];
    const float* ln2_g       = (const float*)d_in[12];
    const float* ln2_b       = (const float*)d_in[13];
    const float* cls_w       = (const float*)d_in[14];  // [256,2]
    const float* cls_b       = (const float*)d_in[15];  // [2]
    float* out = (float*)d_out;

    cudaFuncSetAttribute(k_attn, cudaFuncAttributeMaxDynamicSharedMemorySize, SMEM_A);
    cudaFuncSetAttribute(k_ffn,  cudaFuncAttributeMaxDynamicSharedMemorySize, SMEM_B);

    k_freq<<<1, 128>>>();
    k_embed<<<NROWS, 256>>>(tokens, embed);
    for (int l = 0; l < 2; l++){
        k_attn<<<NROWS/64, 256, SMEM_A>>>(attn_theta + l*64,
                                          combine_w + l*256*256,
                                          combine_b + l*256,
                                          ln1_g + l*256, ln1_b + l*256);
        k_ffn<<<NROWS/64, 256, SMEM_B>>>(ffn_theta + l*8,
                                         lin1_w + l*8*512,
                                         lin1_b + l*512,
                                         lin2_w + l*512*256,
                                         lin2_b + l*256,
                                         ln2_g + l*256, ln2_b + l*256);
    }
    k_cls<<<NBATCH, 256>>>(cls_w, cls_b, out);
}

// round 4
// speedup vs baseline: 2.1470x; 2.1392x over previous
#include <cuda_runtime.h>
#include <math.h>
#include <stdint.h>

#define NBATCH 16
#define SEQ    2048
#define EMB    256
#define NROWS  (NBATCH*SEQ)
#define FFND   512

__device__ float g_x[NROWS*EMB];
__device__ float g_freq[128];
__device__ float g_wt_attn[2*256*256];   // [f][e] transposed, tf32-rounded
__device__ float g_wt_ffn[2*256*FFND];   // [e][f] transposed, tf32-rounded
__device__ float g_pool[512*EMB];

__device__ __forceinline__ float to_tf32(float x){
    uint32_t o; asm("cvt.rna.tf32.f32 %0, %1;" : "=r"(o) : "f"(x));
    return __uint_as_float(o);
}
__device__ __forceinline__ void mma8(float* d, const uint32_t* a, const uint32_t* b){
    asm volatile("mma.sync.aligned.m16n8k8.row.col.f32.tf32.tf32.f32 "
        "{%0,%1,%2,%3}, {%4,%5,%6,%7}, {%8,%9}, {%0,%1,%2,%3};"
        : "+f"(d[0]),"+f"(d[1]),"+f"(d[2]),"+f"(d[3])
        : "r"(a[0]),"r"(a[1]),"r"(a[2]),"r"(a[3]),"r"(b[0]),"r"(b[1]));
}

// ---------------- small kernels ----------------
__global__ void k_freq(){
    int i = threadIdx.x;
    if (i < 128) g_freq[i] = (float)exp(-(double)(2*i) * (log(10000.0) / 256.0));
}
__global__ void k_embed(const int* __restrict__ tokens, const float* __restrict__ embed){
    int row = blockIdx.x, e = threadIdx.x;
    float v = embed[tokens[row]*EMB + e];
    float ang = (float)(row & (SEQ-1)) * g_freq[e >> 1];
    v += (e & 1) ? cosf(ang) : sinf(ang);
    g_x[row*EMB + e] = v;
}
__global__ void k_tr_attn(const float* __restrict__ W){
    int l = blockIdx.y, idx = blockIdx.x*256 + threadIdx.x;
    int e = idx & 255, f = idx >> 8;
    g_wt_attn[l*65536 + f*256 + e] = to_tf32(W[l*65536 + e*256 + f]);
}
__global__ void k_tr_ffn(const float* __restrict__ W2){
    int l = blockIdx.y, idx = blockIdx.x*256 + threadIdx.x;
    int f = idx & 511, e = idx >> 9;
    g_wt_ffn[l*131072 + e*512 + f] = to_tf32(W2[l*131072 + f*256 + e]);
}

// ---------------- smem layout (floats) ----------------
// As [128][36] @0      (4608)
// Bs [256][36] @4608   (9216)  -> 13824
// W1s[8][512]  @13824  (4096)  -> 17920   (ffn only)
// qs [128][8]  @17920  (1024)  -> 18944   (ffn only)
// zbuf [128][264] @0 (alias, after GEMM)  = 33792 floats
#define SM_BYTES 135168

// shared GEMM core pieces as macros to keep both kernels identical in structure
#define MMA_CORE(KCHUNKS)                                                     \
    int tid = threadIdx.x;                                                    \
    int wid = tid >> 5, lane = tid & 31;                                      \
    int gr = lane >> 2, gc = lane & 3;                                        \
    int mBase = (wid & 3) * 32, nBase = (wid >> 2) * 64;                      \
    int row0 = blockIdx.x * 128;                                              \
    float acc[2][8][4];                                                       \
    _Pragma("unroll")                                                         \
    for (int tm=0;tm<2;tm++) _Pragma("unroll")                                \
    for (int tn=0;tn<8;tn++) _Pragma("unroll")                                \
    for (int j=0;j<4;j++) acc[tm][tn][j] = 0.f;

#define MMA_COMPUTE()                                                         \
    __syncthreads();                                                          \
    _Pragma("unroll")                                                         \
    for (int ks = 0; ks < 4; ks++){                                           \
        int k0 = ks*8;                                                        \
        uint32_t a[2][4], b[8][2];                                            \
        _Pragma("unroll")                                                     \
        for (int tm=0;tm<2;tm++){                                             \
            int m0 = (mBase + tm*16 + gr)*36 + k0 + gc;                       \
            a[tm][0] = Asu[m0];        a[tm][1] = Asu[m0 + 8*36];             \
            a[tm][2] = Asu[m0 + 4];    a[tm][3] = Asu[m0 + 8*36 + 4];         \
        }                                                                     \
        _Pragma("unroll")                                                     \
        for (int tn=0;tn<8;tn++){                                             \
            int n0 = (nBase + tn*8 + gr)*36 + k0 + gc;                        \
            b[tn][0] = Bsu[n0];  b[tn][1] = Bsu[n0 + 4];                      \
        }                                                                     \
        _Pragma("unroll")                                                     \
        for (int tm=0;tm<2;tm++) _Pragma("unroll")                            \
        for (int tn=0;tn<8;tn++) mma8(acc[tm][tn], a[tm], b[tn]);             \
    }                                                                         \
    __syncthreads();

#define EPILOGUE_LN(bias, lng, lnb)                                           \
    float* zbuf = sm;                                                         \
    _Pragma("unroll")                                                         \
    for (int tm=0;tm<2;tm++){                                                 \
        int r0 = mBase + tm*16 + gr;                                          \
        _Pragma("unroll")                                                     \
        for (int tn=0;tn<8;tn++){                                             \
            int cA = nBase + tn*8 + 2*gc;                                     \
            float bx = __ldg(&bias[cA]), by = __ldg(&bias[cA+1]);             \
            float2 x0 = *(const float2*)&g_x[(row0+r0)*EMB + cA];             \
            float2 x1 = *(const float2*)&g_x[(row0+r0+8)*EMB + cA];           \
            float2 z0 = make_float2(acc[tm][tn][0]+bx+x0.x, acc[tm][tn][1]+by+x0.y); \
            float2 z1 = make_float2(acc[tm][tn][2]+bx+x1.x, acc[tm][tn][3]+by+x1.y); \
            *(float2*)&zbuf[r0*264 + cA] = z0;                                \
            *(float2*)&zbuf[(r0+8)*264 + cA] = z1;                            \
        }                                                                     \
    }                                                                         \
    __syncthreads();                                                          \
    float gv[8], bv[8];                                                       \
    _Pragma("unroll")                                                         \
    for (int u=0;u<8;u++){ gv[u] = __ldg(&lng[lane+32*u]); bv[u] = __ldg(&lnb[lane+32*u]); } \
    for (int rr = 0; rr < 8; rr++){                                           \
        int r = wid*8 + rr;                                                   \
        float v[8], s = 0.f, q = 0.f;                                         \
        _Pragma("unroll")                                                     \
        for (int u=0;u<8;u++){ v[u] = zbuf[r*264 + lane + 32*u]; s += v[u]; q += v[u]*v[u]; } \
        _Pragma("unroll")                                                     \
        for (int off=16; off; off>>=1){                                       \
            s += __shfl_xor_sync(0xffffffffu, s, off);                        \
            q += __shfl_xor_sync(0xffffffffu, q, off);                        \
        }                                                                     \
        float m = s * (1.f/256.f);                                            \
        float var = fmaxf(q * (1.f/256.f) - m*m, 0.f);                        \
        float rs = rsqrtf(var + 1e-5f);                                       \
        float* xo = g_x + (row0+r)*EMB;                                       \
        _Pragma("unroll")                                                     \
        for (int u=0;u<8;u++) xo[lane+32*u] = (v[u]-m)*rs*gv[u] + bv[u];      \
    }

// ---------------- attn: D = cos(x+theta) @ W ; x = LN(x + D + b) ----------------
__global__ __launch_bounds__(512, 1) void k_attn_mma(int layer,
    const float* __restrict__ attn_theta, const float* __restrict__ combine_b,
    const float* __restrict__ ln1g, const float* __restrict__ ln1b){
    extern __shared__ float sm[];
    float* As = sm;
    float* Bs = sm + 4608;
    const uint32_t* Asu = (const uint32_t*)As;
    const uint32_t* Bsu = (const uint32_t*)Bs;
    const float* theta = attn_theta + layer*64;
    const float* Wt    = g_wt_attn + layer*65536;
    const float* bias  = combine_b + layer*256;
    const float* lng   = ln1g + layer*256;
    const float* lnb   = ln1b + layer*256;

    MMA_CORE(8)
    for (int c = 0; c < 8; c++){
        #pragma unroll
        for (int i = 0; i < 2; i++){
            int idx = tid + 512*i;
            int k4 = (idx & 7)*4, r = idx >> 3;
            int kb = c*32 + k4;
            float4 xv = *(const float4*)&g_x[(row0+r)*EMB + kb];
            float4 av;
            av.x = to_tf32(cosf(xv.x + __ldg(&theta[(kb+0)&63])));
            av.y = to_tf32(cosf(xv.y + __ldg(&theta[(kb+1)&63])));
            av.z = to_tf32(cosf(xv.z + __ldg(&theta[(kb+2)&63])));
            av.w = to_tf32(cosf(xv.w + __ldg(&theta[(kb+3)&63])));
            *(float4*)&As[r*36 + k4] = av;
        }
        #pragma unroll
        for (int i = 0; i < 4; i++){
            int idx = tid + 512*i;
            int k4 = (idx & 7)*4, n = idx >> 3;
            *(float4*)&Bs[n*36 + k4] = *(const float4*)&Wt[n*256 + c*32 + k4];
        }
        MMA_COMPUTE()
    }
    EPILOGUE_LN(bias, lng, lnb)
}

// ---------------- ffn: h=relu(qW1+b1); D = h @ W2 ; x = LN(x + D + b2) ----------------
__global__ __launch_bounds__(512, 1) void k_ffn_mma(int layer,
    const float* __restrict__ ffn_theta, const float* __restrict__ lin1_w,
    const float* __restrict__ lin1_b, const float* __restrict__ lin2_b,
    const float* __restrict__ ln2g, const float* __restrict__ ln2b){
    extern __shared__ float sm[];
    float* As  = sm;
    float* Bs  = sm + 4608;
    float* W1s = sm + 13824;
    float* qs  = sm + 17920;
    const uint32_t* Asu = (const uint32_t*)As;
    const uint32_t* Bsu = (const uint32_t*)Bs;
    const float* fth  = ffn_theta + layer*8;
    const float* W1   = lin1_w + layer*8*FFND;
    const float* b1   = lin1_b + layer*FFND;
    const float* Wt2  = g_wt_ffn + layer*256*FFND;
    const float* bias = lin2_b + layer*256;
    const float* lng  = ln2g + layer*256;
    const float* lnb  = ln2b + layer*256;

    MMA_CORE(16)
    // qs and W1s
    for (int idx = tid; idx < 1024; idx += 512){
        int r = idx >> 3, n = idx & 7;
        qs[idx] = cosf(g_x[(row0+r)*EMB + n]) * cosf(__ldg(&fth[n]));
    }
    {
        const float4* src = (const float4*)W1;
        float4* dst = (float4*)W1s;
        #pragma unroll
        for (int i = 0; i < 2; i++) dst[tid + 512*i] = src[tid + 512*i];
    }
    __syncthreads();

    for (int c = 0; c < 16; c++){
        #pragma unroll
        for (int i = 0; i < 8; i++){
            int idx = tid + 512*i;
            int f = idx & 31, r = idx >> 5;
            float av = __ldg(&b1[c*32 + f]);
            #pragma unroll
            for (int n = 0; n < 8; n++) av += qs[r*8 + n] * W1s[n*512 + c*32 + f];
            As[r*36 + f] = to_tf32(fmaxf(av, 0.f));
        }
        #pragma unroll
        for (int i = 0; i < 4; i++){
            int idx = tid + 512*i;
            int k4 = (idx & 7)*4, n = idx >> 3;
            *(float4*)&Bs[n*36 + k4] = *(const float4*)&Wt2[n*512 + c*32 + k4];
        }
        MMA_COMPUTE()
    }
    EPILOGUE_LN(bias, lng, lnb)
}

// ---------------- pooling + classifier ----------------
__global__ void k_pool(){
    int p = blockIdx.x;
    int b = p >> 5, seg = p & 31;
    const float* xp = g_x + (b*SEQ + seg*64)*EMB + threadIdx.x;
    float s = 0.f;
    #pragma unroll 4
    for (int i = 0; i < 64; i++) s += xp[i*EMB];
    g_pool[p*EMB + threadIdx.x] = s;
}
__global__ void k_cls2(const float* __restrict__ cw, const float* __restrict__ cb,
                       float* __restrict__ out){
    int b = blockIdx.x, tid = threadIdx.x;
    float s = 0.f;
    #pragma unroll
    for (int seg = 0; seg < 32; seg++) s += g_pool[(b*32+seg)*EMB + tid];
    float p = s * (1.f/(float)SEQ);
    float l0 = p * cw[tid*2 + 0];
    float l1 = p * cw[tid*2 + 1];
    #pragma unroll
    for (int off=16; off; off>>=1){
        l0 += __shfl_xor_sync(0xffffffffu, l0, off);
        l1 += __shfl_xor_sync(0xffffffffu, l1, off);
    }
    __shared__ float r0[8], r1[8];
    int warp = tid >> 5, lane = tid & 31;
    if (lane == 0){ r0[warp] = l0; r1[warp] = l1; }
    __syncthreads();
    if (tid == 0){
        float a = cb[0], c = cb[1];
        #pragma unroll
        for (int w = 0; w < 8; w++){ a += r0[w]; c += r1[w]; }
        out[b*2 + 0] = a; out[b*2 + 1] = c;
    }
}

// ---------------- launch ----------------
extern "C" void kernel_launch(void* const* d_in, const int* in_sizes, int n_in,
                              void* d_out, int out_size){
    const int*   tokens     = (const int*)  d_in[0];
    const float* embed      = (const float*)d_in[1];
    const float* attn_theta = (const float*)d_in[2];
    const float* combine_w  = (const float*)d_in[3];
    const float* combine_b  = (const float*)d_in[4];
    const float* ffn_theta  = (const float*)d_in[5];
    const float* lin1_w     = (const float*)d_in[6];
    const float* lin1_b     = (const float*)d_in[7];
    const float* lin2_w     = (const float*)d_in[8];
    const float* lin2_b     = (const float*)d_in[9];
    const float* ln1_g      = (const float*)d_in[10];
    const float* ln1_b      = (const float*)d_in[11];
    const float* ln2_g      = (const float*)d_in[12];
    const float* ln2_b      = (const float*)d_in[13];
    const float* cls_w      = (const float*)d_in[14];
    const float* cls_b      = (const float*)d_in[15];
    float* out = (float*)d_out;

    static int inited = 0;
    if (!inited){
        cudaFuncSetAttribute(k_attn_mma, cudaFuncAttributeMaxDynamicSharedMemorySize, SM_BYTES);
        cudaFuncSetAttribute(k_ffn_mma,  cudaFuncAttributeMaxDynamicSharedMemorySize, SM_BYTES);
        inited = 1;
    }

    k_freq<<<1, 128>>>();
    {
        dim3 ga(256, 2); k_tr_attn<<<ga, 256>>>(combine_w);
        dim3 gf(512, 2); k_tr_ffn<<<gf, 256>>>(lin2_w);
    }
    k_embed<<<NROWS, 256>>>(tokens, embed);
    for (int l = 0; l < 2; l++){
        k_attn_mma<<<NROWS/128, 512, SM_BYTES>>>(l, attn_theta, combine_b, ln1_g, ln1_b);
        k_ffn_mma <<<NROWS/128, 512, SM_BYTES>>>(l, ffn_theta, lin1_w, lin1_b, lin2_b, ln2_g, ln2_b);
    }
    k_pool<<<512, 256>>>();
    k_cls2<<<NBATCH, 256>>>(cls_w, cls_b, out);
}

// round 5
// speedup vs baseline: 2.4849x; 1.1574x over previous
#include <cuda_runtime.h>
#include <math.h>
#include <stdint.h>

#define NBATCH 16
#define SEQ    2048
#define EMB    256
#define NROWS  (NBATCH*SEQ)
#define FFND   512

__device__ float g_x[NROWS*EMB];
__device__ float g_freq[128];
__device__ float g_wt_attn[2*256*256];   // [f][e_perm] transposed, tf32-rounded, pair-permuted
__device__ float g_wt_ffn[2*256*FFND];   // [e][f_perm]
__device__ float g_pool[512*EMB];

__device__ __forceinline__ float to_tf32(float x){
    uint32_t o; asm("cvt.rna.tf32.f32 %0, %1;" : "=r"(o) : "f"(x));
    return __uint_as_float(o);
}
__device__ __forceinline__ void mma8(float* d, const uint32_t* a, const uint32_t* b){
    asm volatile("mma.sync.aligned.m16n8k8.row.col.f32.tf32.tf32.f32 "
        "{%0,%1,%2,%3}, {%4,%5,%6,%7}, {%8,%9}, {%0,%1,%2,%3};"
        : "+f"(d[0]),"+f"(d[1]),"+f"(d[2]),"+f"(d[3])
        : "r"(a[0]),"r"(a[1]),"r"(a[2]),"r"(a[3]),"r"(b[0]),"r"(b[1]));
}
__device__ __forceinline__ uint32_t smem_u32(const void* p){
    uint32_t a;
    asm("{ .reg .u64 t; cvta.to.shared.u64 t, %1; cvt.u32.u64 %0, t; }" : "=r"(a) : "l"(p));
    return a;
}
__device__ __forceinline__ void cpasync16(uint32_t dst, const void* src){
    asm volatile("cp.async.cg.shared.global [%0], [%1], 16;" :: "r"(dst), "l"(src));
}
__device__ __forceinline__ void cpcommit(){ asm volatile("cp.async.commit_group;" ::: "memory"); }
__device__ __forceinline__ void cpwait0(){ asm volatile("cp.async.wait_group 0;" ::: "memory"); }

// pair-permutation within each 8-group: k -> (k&~7) + (k&3)*2 + ((k>>2)&1)
__device__ __forceinline__ int kperm(int k){ return (k & ~7) + (k&3)*2 + ((k>>2)&1); }

// ---------------- small kernels ----------------
__global__ void k_freq(){
    int i = threadIdx.x;
    if (i < 128) g_freq[i] = (float)exp(-(double)(2*i) * (log(10000.0) / 256.0));
}
__global__ void k_embed(const int* __restrict__ tokens, const float* __restrict__ embed){
    int g = blockIdx.x*256 + threadIdx.x;      // 2M float4 groups
    int row = g >> 6, c4 = (g & 63) * 4;
    int tok = __ldg(&tokens[row]);
    float4 v = *(const float4*)&embed[tok*EMB + c4];
    float pos = (float)(row & (SEQ-1));
    float s0,c0,s1,c1;
    sincosf(pos * g_freq[(c4>>1)+0], &s0, &c0);
    sincosf(pos * g_freq[(c4>>1)+1], &s1, &c1);
    v.x += s0; v.y += c0; v.z += s1; v.w += c1;
    *(float4*)&g_x[row*EMB + c4] = v;
}
__global__ void k_tr_attn(const float* __restrict__ W){
    int l = blockIdx.y, idx = blockIdx.x*256 + threadIdx.x;
    int e = idx & 255, f = idx >> 8;
    g_wt_attn[l*65536 + f*256 + kperm(e)] = to_tf32(W[l*65536 + e*256 + f]);
}
__global__ void k_tr_ffn(const float* __restrict__ W2){
    int l = blockIdx.y, idx = blockIdx.x*256 + threadIdx.x;
    int f = idx & 511, e = idx >> 9;
    g_wt_ffn[l*131072 + e*512 + kperm(f)] = to_tf32(W2[l*131072 + f*256 + e]);
}

// ---------------- smem layout (floats) ----------------
// As0 [0,5120) As1 [5120,10240)  (128 rows x 40)
// Bs0 [10240,20480) Bs1 [20480,30720)  (256 rows x 40)
// ffn extra: W1s [30720,34816), qs [34816,35840)
// zbuf [0, 33792) aliases (epilogue only)
#define SM_ATTN 135168
#define SM_FFN  143360

// ---------------- MMA chunk core ----------------
__device__ __forceinline__ void mma_chunk(const float* __restrict__ As,
                                          const float* __restrict__ Bs,
                                          int wm, int wn, int gr, int gc,
                                          float acc[4][8][4]){
    #pragma unroll
    for (int ks = 0; ks < 4; ks++){
        float2 a[4][2], b[8];
        #pragma unroll
        for (int tm = 0; tm < 4; tm++){
            int r0 = wm*64 + tm*16 + gr;
            a[tm][0] = *(const float2*)&As[r0*40 + ks*8 + gc*2];
            a[tm][1] = *(const float2*)&As[(r0+8)*40 + ks*8 + gc*2];
        }
        #pragma unroll
        for (int tn = 0; tn < 8; tn++){
            int n0 = wn*64 + tn*8 + gr;
            b[tn] = *(const float2*)&Bs[n0*40 + ks*8 + gc*2];
        }
        #pragma unroll
        for (int tm = 0; tm < 4; tm++){
            uint32_t av[4] = { __float_as_uint(a[tm][0].x), __float_as_uint(a[tm][1].x),
                               __float_as_uint(a[tm][0].y), __float_as_uint(a[tm][1].y) };
            #pragma unroll
            for (int tn = 0; tn < 8; tn++){
                uint32_t bv[2] = { __float_as_uint(b[tn].x), __float_as_uint(b[tn].y) };
                mma8(acc[tm][tn], av, bv);
            }
        }
    }
}

// ---------------- staging ----------------
__device__ __forceinline__ void stageB_async(uint32_t bs_u32, const float* __restrict__ Wt,
                                             int rowlen, int c, int tid){
    #pragma unroll
    for (int i = 0; i < 8; i++){
        int idx = tid + 256*i;
        int seg = idx & 7, n = idx >> 3;
        cpasync16(bs_u32 + (uint32_t)(n*160 + seg*16), Wt + n*rowlen + c*32 + seg*4);
    }
}
__device__ __forceinline__ void attnA_regs(int row0, int c, int tid,
                                           const float* __restrict__ theta, float4* av){
    #pragma unroll
    for (int i = 0; i < 4; i++){
        int idx = tid + 256*i;
        int kk4 = (idx & 7)*4, r = idx >> 3;
        int kb = c*32 + kk4;
        float4 xv = *(const float4*)&g_x[(row0+r)*EMB + kb];
        av[i].x = to_tf32(__cosf(xv.x + __ldg(&theta[(kb+0)&63])));
        av[i].y = to_tf32(__cosf(xv.y + __ldg(&theta[(kb+1)&63])));
        av[i].z = to_tf32(__cosf(xv.z + __ldg(&theta[(kb+2)&63])));
        av[i].w = to_tf32(__cosf(xv.w + __ldg(&theta[(kb+3)&63])));
    }
}
__device__ __forceinline__ void attnA_sts(float* __restrict__ As, int tid, const float4* av){
    #pragma unroll
    for (int i = 0; i < 4; i++){
        int idx = tid + 256*i;
        int kk4 = (idx & 7)*4, r = idx >> 3;
        float* p = &As[r*40 + (kk4 & ~7) + ((kk4>>2)&1)];
        p[0] = av[i].x; p[2] = av[i].y; p[4] = av[i].z; p[6] = av[i].w;
    }
}
__device__ __forceinline__ void ffnA_stage(float* __restrict__ As,
        const float* __restrict__ qs, const float* __restrict__ W1s,
        const float* __restrict__ b1, int c, int tid){
    #pragma unroll
    for (int i = 0; i < 16; i++){
        int idx = tid + 256*i;
        int f = idx & 31, r = idx >> 5;
        float a = __ldg(&b1[c*32 + f]);
        #pragma unroll
        for (int n = 0; n < 8; n++) a += qs[r*8 + n] * W1s[n*512 + c*32 + f];
        As[r*40 + kperm(f)] = to_tf32(fmaxf(a, 0.f));
    }
}

// ---------------- epilogue: x = LN(x + D + bias) ----------------
#define EPILOGUE_LN(bias, lng, lnb)                                           \
    float* zbuf = sm;                                                         \
    _Pragma("unroll")                                                         \
    for (int tm=0;tm<4;tm++){                                                 \
        int r0 = wm*64 + tm*16 + gr;                                          \
        _Pragma("unroll")                                                     \
        for (int tn=0;tn<8;tn++){                                             \
            int cA = wn*64 + tn*8 + 2*gc;                                     \
            float bx = __ldg(&bias[cA]), by = __ldg(&bias[cA+1]);             \
            float2 x0 = *(const float2*)&g_x[(row0+r0)*EMB + cA];             \
            float2 x1 = *(const float2*)&g_x[(row0+r0+8)*EMB + cA];           \
            *(float2*)&zbuf[r0*264 + cA] =                                    \
                make_float2(acc[tm][tn][0]+bx+x0.x, acc[tm][tn][1]+by+x0.y);  \
            *(float2*)&zbuf[(r0+8)*264 + cA] =                                \
                make_float2(acc[tm][tn][2]+bx+x1.x, acc[tm][tn][3]+by+x1.y);  \
        }                                                                     \
    }                                                                         \
    __syncthreads();                                                          \
    float gv[8], bv[8];                                                       \
    _Pragma("unroll")                                                         \
    for (int u=0;u<8;u++){ gv[u] = __ldg(&lng[lane+32*u]); bv[u] = __ldg(&lnb[lane+32*u]); } \
    for (int rr = 0; rr < 16; rr++){                                          \
        int r = wid*16 + rr;                                                  \
        float v[8], s = 0.f, q = 0.f;                                         \
        _Pragma("unroll")                                                     \
        for (int u=0;u<8;u++){ v[u] = zbuf[r*264 + lane + 32*u]; s += v[u]; q += v[u]*v[u]; } \
        _Pragma("unroll")                                                     \
        for (int off=16; off; off>>=1){                                       \
            s += __shfl_xor_sync(0xffffffffu, s, off);                        \
            q += __shfl_xor_sync(0xffffffffu, q, off);                        \
        }                                                                     \
        float m = s * (1.f/256.f);                                            \
        float var = fmaxf(q * (1.f/256.f) - m*m, 0.f);                        \
        float rs = rsqrtf(var + 1e-5f);                                       \
        float* xo = g_x + (row0+r)*EMB;                                       \
        _Pragma("unroll")                                                     \
        for (int u=0;u<8;u++) xo[lane+32*u] = (v[u]-m)*rs*gv[u] + bv[u];      \
    }

#define GEMM_SETUP()                                                          \
    int tid = threadIdx.x;                                                    \
    int wid = tid >> 5, lane = tid & 31;                                      \
    int gr = lane >> 2, gc = lane & 3;                                        \
    int wm = wid & 1, wn = wid >> 1;                                          \
    int row0 = blockIdx.x * 128;                                              \
    float acc[4][8][4];                                                       \
    _Pragma("unroll")                                                         \
    for (int tm=0;tm<4;tm++) _Pragma("unroll")                                \
    for (int tn=0;tn<8;tn++) _Pragma("unroll")                                \
    for (int j=0;j<4;j++) acc[tm][tn][j] = 0.f;

// ---------------- attn: D = cos(x+theta) @ W ; x = LN(x + D + b) ----------------
__global__ __launch_bounds__(256, 1) void k_attn_mma(int layer,
    const float* __restrict__ attn_theta, const float* __restrict__ combine_b,
    const float* __restrict__ ln1g, const float* __restrict__ ln1b){
    extern __shared__ float sm[];
    float* As = sm;                 // 2 x 5120
    float* Bs = sm + 10240;         // 2 x 10240
    uint32_t bs_u32 = smem_u32(Bs);
    const float* theta = attn_theta + layer*64;
    const float* Wt    = g_wt_attn + layer*65536;
    const float* bias  = combine_b + layer*256;
    const float* lng   = ln1g + layer*256;
    const float* lnb   = ln1b + layer*256;

    GEMM_SETUP()
    float4 av[4];
    attnA_regs(row0, 0, tid, theta, av);
    stageB_async(bs_u32, Wt, 256, 0, tid);
    cpcommit();
    attnA_sts(As, tid, av);
    cpwait0(); __syncthreads();

    for (int c = 0; c < 8; c++){
        int cur = c & 1, nxt = cur ^ 1;
        if (c + 1 < 8){
            stageB_async(bs_u32 + nxt*40960u, Wt, 256, c+1, tid);
            cpcommit();
            attnA_regs(row0, c+1, tid, theta, av);
        }
        mma_chunk(As + cur*5120, Bs + cur*10240, wm, wn, gr, gc, acc);
        if (c + 1 < 8){
            attnA_sts(As + nxt*5120, tid, av);
            cpwait0();
        }
        __syncthreads();
    }
    EPILOGUE_LN(bias, lng, lnb)
}

// ---------------- ffn ----------------
__global__ __launch_bounds__(256, 1) void k_ffn_mma(int layer,
    const float* __restrict__ ffn_theta, const float* __restrict__ lin1_w,
    const float* __restrict__ lin1_b, const float* __restrict__ lin2_b,
    const float* __restrict__ ln2g, const float* __restrict__ ln2b){
    extern __shared__ float sm[];
    float* As  = sm;
    float* Bs  = sm + 10240;
    float* W1s = sm + 30720;
    float* qs  = sm + 34816;
    uint32_t bs_u32 = smem_u32(Bs);
    const float* fth  = ffn_theta + layer*8;
    const float* W1   = lin1_w + layer*8*FFND;
    const float* b1   = lin1_b + layer*FFND;
    const float* Wt2  = g_wt_ffn + layer*256*FFND;
    const float* bias = lin2_b + layer*256;
    const float* lng  = ln2g + layer*256;
    const float* lnb  = ln2b + layer*256;

    GEMM_SETUP()
    for (int idx = tid; idx < 1024; idx += 256){
        int r = idx >> 3, n = idx & 7;
        qs[idx] = __cosf(g_x[(row0+r)*EMB + n]) * __cosf(__ldg(&fth[n]));
    }
    {
        const float4* src = (const float4*)W1;
        float4* dst = (float4*)W1s;
        #pragma unroll
        for (int i = 0; i < 4; i++) dst[tid + 256*i] = src[tid + 256*i];
    }
    stageB_async(bs_u32, Wt2, 512, 0, tid);
    cpcommit();
    __syncthreads();
    ffnA_stage(As, qs, W1s, b1, 0, tid);
    cpwait0(); __syncthreads();

    for (int c = 0; c < 16; c++){
        int cur = c & 1, nxt = cur ^ 1;
        if (c + 1 < 16){
            stageB_async(bs_u32 + nxt*40960u, Wt2, 512, c+1, tid);
            cpcommit();
        }
        mma_chunk(As + cur*5120, Bs + cur*10240, wm, wn, gr, gc, acc);
        if (c + 1 < 16){
            ffnA_stage(As + nxt*5120, qs, W1s, b1, c+1, tid);
            cpwait0();
        }
        __syncthreads();
    }
    EPILOGUE_LN(bias, lng, lnb)
}

// ---------------- pooling + classifier ----------------
__global__ void k_pool(){
    int p = blockIdx.x;
    int b = p >> 5, seg = p & 31;
    const float* xp = g_x + (b*SEQ + seg*64)*EMB + threadIdx.x;
    float s = 0.f;
    #pragma unroll 4
    for (int i = 0; i < 64; i++) s += xp[i*EMB];
    g_pool[p*EMB + threadIdx.x] = s;
}
__global__ void k_cls2(const float* __restrict__ cw, const float* __restrict__ cb,
                       float* __restrict__ out){
    int b = blockIdx.x, tid = threadIdx.x;
    float s = 0.f;
    #pragma unroll
    for (int seg = 0; seg < 32; seg++) s += g_pool[(b*32+seg)*EMB + tid];
    float p = s * (1.f/(float)SEQ);
    float l0 = p * cw[tid*2 + 0];
    float l1 = p * cw[tid*2 + 1];
    #pragma unroll
    for (int off=16; off; off>>=1){
        l0 += __shfl_xor_sync(0xffffffffu, l0, off);
        l1 += __shfl_xor_sync(0xffffffffu, l1, off);
    }
    __shared__ float r0[8], r1[8];
    int warp = tid >> 5, lane = tid & 31;
    if (lane == 0){ r0[warp] = l0; r1[warp] = l1; }
    __syncthreads();
    if (tid == 0){
        float a = cb[0], c = cb[1];
        #pragma unroll
        for (int w = 0; w < 8; w++){ a += r0[w]; c += r1[w]; }
        out[b*2 + 0] = a; out[b*2 + 1] = c;
    }
}

// ---------------- launch ----------------
extern "C" void kernel_launch(void* const* d_in, const int* in_sizes, int n_in,
                              void* d_out, int out_size){
    const int*   tokens     = (const int*)  d_in[0];
    const float* embed      = (const float*)d_in[1];
    const float* attn_theta = (const float*)d_in[2];
    const float* combine_w  = (const float*)d_in[3];
    const float* combine_b  = (const float*)d_in[4];
    const float* ffn_theta  = (const float*)d_in[5];
    const float* lin1_w     = (const float*)d_in[6];
    const float* lin1_b     = (const float*)d_in[7];
    const float* lin2_w     = (const float*)d_in[8];
    const float* lin2_b     = (const float*)d_in[9];
    const float* ln1_g      = (const float*)d_in[10];
    const float* ln1_b      = (const float*)d_in[11];
    const float* ln2_g      = (const float*)d_in[12];
    const float* ln2_b      = (const float*)d_in[13];
    const float* cls_w      = (const float*)d_in[14];
    const float* cls_b      = (const float*)d_in[15];
    float* out = (float*)d_out;

    static int inited = 0;
    if (!inited){
        cudaFuncSetAttribute(k_attn_mma, cudaFuncAttributeMaxDynamicSharedMemorySize, SM_ATTN);
        cudaFuncSetAttribute(k_ffn_mma,  cudaFuncAttributeMaxDynamicSharedMemorySize, SM_FFN);
        inited = 1;
    }

    k_freq<<<1, 128>>>();
    {
        dim3 ga(256, 2); k_tr_attn<<<ga, 256>>>(combine_w);
        dim3 gf(512, 2); k_tr_ffn<<<gf, 256>>>(lin2_w);
    }
    k_embed<<<NROWS/4, 256>>>(tokens, embed);
    for (int l = 0; l < 2; l++){
        k_attn_mma<<<NROWS/128, 256, SM_ATTN>>>(l, attn_theta, combine_b, ln1_g, ln1_b);
        k_ffn_mma <<<NROWS/128, 256, SM_FFN >>>(l, ffn_theta, lin1_w, lin1_b, lin2_b, ln2_g, ln2_b);
    }
    k_pool<<<512, 256>>>();
    k_cls2<<<NBATCH, 256>>>(cls_w, cls_b, out);
}

// round 6
// speedup vs baseline: 3.3779x; 1.3594x over previous
#include <cuda_runtime.h>
#include <cuda_fp16.h>
#include <math.h>
#include <stdint.h>

#define NBATCH 16
#define SEQ    2048
#define EMB    256
#define NROWS  (NBATCH*SEQ)
#define FFND   512

__device__ float  g_x[NROWS*EMB];
__device__ float  g_freq[128];
__device__ __half g_wt_attn[2*256*256];   // [f][e] transposed, fp16
__device__ __half g_wt_ffn[2*256*FFND];   // [e][f] transposed, fp16
__device__ float  g_pool[512*EMB];

__device__ __forceinline__ void mma16(float* d, const uint32_t* a, const uint32_t* b){
    asm volatile("mma.sync.aligned.m16n8k16.row.col.f32.f16.f16.f32 "
        "{%0,%1,%2,%3}, {%4,%5,%6,%7}, {%8,%9}, {%0,%1,%2,%3};"
        : "+f"(d[0]),"+f"(d[1]),"+f"(d[2]),"+f"(d[3])
        : "r"(a[0]),"r"(a[1]),"r"(a[2]),"r"(a[3]),"r"(b[0]),"r"(b[1]));
}
__device__ __forceinline__ uint32_t smem_u32(const void* p){
    uint32_t a;
    asm("{ .reg .u64 t; cvta.to.shared.u64 t, %1; cvt.u32.u64 %0, t; }" : "=r"(a) : "l"(p));
    return a;
}
__device__ __forceinline__ void cpasync16(uint32_t dst, const void* src){
    asm volatile("cp.async.cg.shared.global [%0], [%1], 16;" :: "r"(dst), "l"(src));
}
__device__ __forceinline__ void cpcommit(){ asm volatile("cp.async.commit_group;" ::: "memory"); }
__device__ __forceinline__ void cpwait0(){ asm volatile("cp.async.wait_group 0;" ::: "memory"); }

// ---------------- small kernels ----------------
__global__ void k_freq(){
    int i = threadIdx.x;
    if (i < 128) g_freq[i] = (float)exp(-(double)(2*i) * (log(10000.0) / 256.0));
}
__global__ void k_embed(const int* __restrict__ tokens, const float* __restrict__ embed){
    int g = blockIdx.x*256 + threadIdx.x;
    int row = g >> 6, c4 = (g & 63) * 4;
    int tok = __ldg(&tokens[row]);
    float4 v = *(const float4*)&embed[tok*EMB + c4];
    float pos = (float)(row & (SEQ-1));
    float s0,c0,s1,c1;
    sincosf(pos * g_freq[(c4>>1)+0], &s0, &c0);
    sincosf(pos * g_freq[(c4>>1)+1], &s1, &c1);
    v.x += s0; v.y += c0; v.z += s1; v.w += c1;
    *(float4*)&g_x[row*EMB + c4] = v;
}
__global__ void k_tr_attn(const float* __restrict__ W){
    int l = blockIdx.y, idx = blockIdx.x*256 + threadIdx.x;
    int e = idx & 255, f = idx >> 8;
    g_wt_attn[l*65536 + f*256 + e] = __float2half_rn(W[l*65536 + e*256 + f]);
}
__global__ void k_tr_ffn(const float* __restrict__ W2){
    int l = blockIdx.y, idx = blockIdx.x*256 + threadIdx.x;
    int f = idx & 511, e = idx >> 9;
    g_wt_ffn[l*131072 + e*512 + f] = __float2half_rn(W2[l*131072 + f*256 + e]);
}

// ---------------- smem layout (bytes) ----------------
// As0 @0 (128x40 half = 10240) As1 @10240
// Bs0 @20480 (256x40 half = 20480) Bs1 @40960  -> 61440
// ffn: W1s @61440 (8x512 f32 = 16384), qs @77824 (128x9 f32 = 4608) -> 82432
// epilogue sums reuse @0 (4KB)
#define SM_ATTN 61440
#define SM_FFN  82432

// ---------------- MMA chunk (K=32, two k16 steps) ----------------
__device__ __forceinline__ void mma_chunk(const __half* __restrict__ As,
                                          const __half* __restrict__ Bs,
                                          int wm, int wn, int gid, int tig,
                                          float acc[4][8][4]){
    #pragma unroll
    for (int ks = 0; ks < 2; ks++){
        int k0 = ks*16 + 2*tig;
        uint32_t a[4][4], b[8][2];
        #pragma unroll
        for (int tm = 0; tm < 4; tm++){
            int r_lo = wm*64 + tm*16 + gid;
            a[tm][0] = *(const uint32_t*)&As[r_lo*40 + k0];
            a[tm][1] = *(const uint32_t*)&As[(r_lo+8)*40 + k0];
            a[tm][2] = *(const uint32_t*)&As[r_lo*40 + k0 + 8];
            a[tm][3] = *(const uint32_t*)&As[(r_lo+8)*40 + k0 + 8];
        }
        #pragma unroll
        for (int tn = 0; tn < 8; tn++){
            int n0 = wn*64 + tn*8 + gid;
            b[tn][0] = *(const uint32_t*)&Bs[n0*40 + k0];
            b[tn][1] = *(const uint32_t*)&Bs[n0*40 + k0 + 8];
        }
        #pragma unroll
        for (int tm = 0; tm < 4; tm++)
            #pragma unroll
            for (int tn = 0; tn < 8; tn++) mma16(acc[tm][tn], a[tm], b[tn]);
    }
}

// ---------------- staging ----------------
__device__ __forceinline__ void stageB_async(uint32_t bs_u32, const __half* __restrict__ Wt,
                                             int rowlen, int c, int tid){
    #pragma unroll
    for (int i = 0; i < 4; i++){
        int idx = tid + 256*i;
        int seg = idx & 3, n = idx >> 2;
        cpasync16(bs_u32 + (uint32_t)(n*80 + seg*16), Wt + n*rowlen + c*32 + seg*8);
    }
}
__device__ __forceinline__ void attnA_regs(int row0, int c, int tid,
                                           const float* __restrict__ theta, uint2* av){
    #pragma unroll
    for (int i = 0; i < 4; i++){
        int idx = tid + 256*i;
        int kk4 = (idx & 7)*4, r = idx >> 3;
        int kb = c*32 + kk4;
        float4 xv = *(const float4*)&g_x[(row0+r)*EMB + kb];
        __half2 h01 = __floats2half2_rn(__cosf(xv.x + __ldg(&theta[(kb+0)&63])),
                                        __cosf(xv.y + __ldg(&theta[(kb+1)&63])));
        __half2 h23 = __floats2half2_rn(__cosf(xv.z + __ldg(&theta[(kb+2)&63])),
                                        __cosf(xv.w + __ldg(&theta[(kb+3)&63])));
        av[i].x = *(const uint32_t*)&h01;
        av[i].y = *(const uint32_t*)&h23;
    }
}
__device__ __forceinline__ void attnA_sts(__half* __restrict__ As, int tid, const uint2* av){
    #pragma unroll
    for (int i = 0; i < 4; i++){
        int idx = tid + 256*i;
        int kk4 = (idx & 7)*4, r = idx >> 3;
        *(uint2*)&As[r*40 + kk4] = av[i];
    }
}
// thread -> f = tid&31 (W1 col cached in regs), rows rg*16..+15 (q reads are broadcasts)
__device__ __forceinline__ void ffnA_stage(__half* __restrict__ As,
        const float* __restrict__ qs, const float* __restrict__ W1s,
        const float* __restrict__ b1, int c, int tid){
    int f0 = tid & 31, rg = tid >> 5;
    float wcol[8];
    #pragma unroll
    for (int n = 0; n < 8; n++) wcol[n] = W1s[n*512 + c*32 + f0];
    float bf = __ldg(&b1[c*32 + f0]);
    #pragma unroll
    for (int rr = 0; rr < 16; rr++){
        int r = rg*16 + rr;
        float a = bf;
        #pragma unroll
        for (int n = 0; n < 8; n++) a += qs[r*9 + n] * wcol[n];
        As[r*40 + f0] = __float2half_rn(fmaxf(a, 0.f));
    }
}

// ---------------- register-resident epilogue: x = LN(x + D + bias) ----------------
__device__ __forceinline__ void epilogue(char* sm, float acc[4][8][4],
        int row0, int wm, int wn, int gid, int tig,
        const float* __restrict__ bias, const float* __restrict__ lng,
        const float* __restrict__ lnb){
    // acc += bias + residual
    #pragma unroll
    for (int tm = 0; tm < 4; tm++){
        int r_lo = row0 + wm*64 + tm*16 + gid;
        #pragma unroll
        for (int tn = 0; tn < 8; tn++){
            int col = wn*64 + tn*8 + 2*tig;
            float bx = __ldg(&bias[col]), by = __ldg(&bias[col+1]);
            float2 x0 = *(const float2*)&g_x[r_lo*EMB + col];
            float2 x1 = *(const float2*)&g_x[(r_lo+8)*EMB + col];
            acc[tm][tn][0] += bx + x0.x; acc[tm][tn][1] += by + x0.y;
            acc[tm][tn][2] += bx + x1.x; acc[tm][tn][3] += by + x1.y;
        }
    }
    // per-row partial sums over this warp's 64 cols
    float s[4][2], q[4][2];
    #pragma unroll
    for (int tm = 0; tm < 4; tm++){
        s[tm][0] = s[tm][1] = q[tm][0] = q[tm][1] = 0.f;
        #pragma unroll
        for (int tn = 0; tn < 8; tn++){
            s[tm][0] += acc[tm][tn][0] + acc[tm][tn][1];
            q[tm][0] += acc[tm][tn][0]*acc[tm][tn][0] + acc[tm][tn][1]*acc[tm][tn][1];
            s[tm][1] += acc[tm][tn][2] + acc[tm][tn][3];
            q[tm][1] += acc[tm][tn][2]*acc[tm][tn][2] + acc[tm][tn][3]*acc[tm][tn][3];
        }
    }
    #pragma unroll
    for (int off = 1; off <= 2; off <<= 1)
        #pragma unroll
        for (int tm = 0; tm < 4; tm++)
            #pragma unroll
            for (int h = 0; h < 2; h++){
                s[tm][h] += __shfl_xor_sync(0xffffffffu, s[tm][h], off);
                q[tm][h] += __shfl_xor_sync(0xffffffffu, q[tm][h], off);
            }
    float* S = (float*)sm;   // [128][8]: (s,q) per wn
    if (tig == 0){
        #pragma unroll
        for (int tm = 0; tm < 4; tm++){
            int rl = wm*64 + tm*16 + gid;
            S[rl*8 + wn*2]       = s[tm][0];
            S[rl*8 + wn*2 + 1]   = q[tm][0];
            S[(rl+8)*8 + wn*2]   = s[tm][1];
            S[(rl+8)*8 + wn*2+1] = q[tm][1];
        }
    }
    __syncthreads();
    float2 gv[8], bv[8];
    #pragma unroll
    for (int tn = 0; tn < 8; tn++){
        int col = wn*64 + tn*8 + 2*tig;
        gv[tn] = *(const float2*)&lng[col];
        bv[tn] = *(const float2*)&lnb[col];
    }
    #pragma unroll
    for (int tm = 0; tm < 4; tm++){
        int rl = wm*64 + tm*16 + gid;
        #pragma unroll
        for (int h = 0; h < 2; h++){
            int r = rl + 8*h;
            float Ss = S[r*8+0] + S[r*8+2] + S[r*8+4] + S[r*8+6];
            float Qq = S[r*8+1] + S[r*8+3] + S[r*8+5] + S[r*8+7];
            float m  = Ss * (1.f/256.f);
            float var = fmaxf(Qq * (1.f/256.f) - m*m, 0.f);
            float rs = rsqrtf(var + 1e-5f);
            #pragma unroll
            for (int tn = 0; tn < 8; tn++){
                int col = wn*64 + tn*8 + 2*tig;
                float z0 = acc[tm][tn][2*h], z1 = acc[tm][tn][2*h+1];
                float2 o = make_float2((z0-m)*rs*gv[tn].x + bv[tn].x,
                                       (z1-m)*rs*gv[tn].y + bv[tn].y);
                *(float2*)&g_x[(row0+r)*EMB + col] = o;
            }
        }
    }
}

#define GEMM_SETUP()                                                          \
    int tid = threadIdx.x;                                                    \
    int wid = tid >> 5, lane = tid & 31;                                      \
    int gid = lane >> 2, tig = lane & 3;                                      \
    int wm = wid & 1, wn = wid >> 1;                                          \
    int row0 = blockIdx.x * 128;                                              \
    float acc[4][8][4];                                                       \
    _Pragma("unroll")                                                         \
    for (int tm=0;tm<4;tm++) _Pragma("unroll")                                \
    for (int tn=0;tn<8;tn++) _Pragma("unroll")                                \
    for (int j=0;j<4;j++) acc[tm][tn][j] = 0.f;                               \
    (void)wid;

// ---------------- attn ----------------
__global__ __launch_bounds__(256, 1) void k_attn_mma(int layer,
    const float* __restrict__ attn_theta, const float* __restrict__ combine_b,
    const float* __restrict__ ln1g, const float* __restrict__ ln1b){
    extern __shared__ char sm[];
    __half* As = (__half*)sm;             // 2 x 5120 halves
    __half* Bs = (__half*)(sm + 20480);   // 2 x 10240 halves
    uint32_t bs_u32 = smem_u32(Bs);
    const float*  theta = attn_theta + layer*64;
    const __half* Wt    = g_wt_attn + layer*65536;

    GEMM_SETUP()
    uint2 av[4];
    attnA_regs(row0, 0, tid, theta, av);
    stageB_async(bs_u32, Wt, 256, 0, tid);
    cpcommit();
    attnA_sts(As, tid, av);
    cpwait0(); __syncthreads();

    for (int c = 0; c < 8; c++){
        int cur = c & 1, nxt = cur ^ 1;
        if (c + 1 < 8){
            stageB_async(bs_u32 + nxt*20480u, Wt, 256, c+1, tid);
            cpcommit();
            attnA_regs(row0, c+1, tid, theta, av);
        }
        mma_chunk(As + cur*5120, Bs + cur*10240, wm, wn, gid, tig, acc);
        if (c + 1 < 8){
            attnA_sts(As + nxt*5120, tid, av);
            cpwait0();
        }
        __syncthreads();
    }
    epilogue(sm, acc, row0, wm, wn, gid, tig,
             combine_b + layer*256, ln1g + layer*256, ln1b + layer*256);
}

// ---------------- ffn ----------------
__global__ __launch_bounds__(256, 1) void k_ffn_mma(int layer,
    const float* __restrict__ ffn_theta, const float* __restrict__ lin1_w,
    const float* __restrict__ lin1_b, const float* __restrict__ lin2_b,
    const float* __restrict__ ln2g, const float* __restrict__ ln2b){
    extern __shared__ char sm[];
    __half* As  = (__half*)sm;
    __half* Bs  = (__half*)(sm + 20480);
    float*  W1s = (float*)(sm + 61440);
    float*  qs  = (float*)(sm + 77824);
    uint32_t bs_u32 = smem_u32(Bs);
    const float*  fth = ffn_theta + layer*8;
    const float*  W1  = lin1_w + layer*8*FFND;
    const float*  b1  = lin1_b + layer*FFND;
    const __half* Wt2 = g_wt_ffn + layer*256*FFND;

    GEMM_SETUP()
    for (int idx = tid; idx < 1024; idx += 256){
        int r = idx >> 3, n = idx & 7;
        qs[r*9 + n] = __cosf(g_x[(row0+r)*EMB + n]) * __cosf(__ldg(&fth[n]));
    }
    {
        const float4* src = (const float4*)W1;
        float4* dst = (float4*)W1s;
        #pragma unroll
        for (int i = 0; i < 4; i++) dst[tid + 256*i] = src[tid + 256*i];
    }
    stageB_async(bs_u32, Wt2, 512, 0, tid);
    cpcommit();
    __syncthreads();
    ffnA_stage(As, qs, W1s, b1, 0, tid);
    cpwait0(); __syncthreads();

    for (int c = 0; c < 16; c++){
        int cur = c & 1, nxt = cur ^ 1;
        if (c + 1 < 16){
            stageB_async(bs_u32 + nxt*20480u, Wt2, 512, c+1, tid);
            cpcommit();
        }
        mma_chunk(As + cur*5120, Bs + cur*10240, wm, wn, gid, tig, acc);
        if (c + 1 < 16){
            ffnA_stage(As + nxt*5120, qs, W1s, b1, c+1, tid);
            cpwait0();
        }
        __syncthreads();
    }
    epilogue(sm, acc, row0, wm, wn, gid, tig,
             lin2_b + layer*256, ln2g + layer*256, ln2b + layer*256);
}

// ---------------- pooling + classifier ----------------
__global__ void k_pool(){
    int p = blockIdx.x;
    int b = p >> 5, seg = p & 31;
    const float* xp = g_x + (b*SEQ + seg*64)*EMB + threadIdx.x;
    float s = 0.f;
    #pragma unroll 4
    for (int i = 0; i < 64; i++) s += xp[i*EMB];
    g_pool[p*EMB + threadIdx.x] = s;
}
__global__ void k_cls2(const float* __restrict__ cw, const float* __restrict__ cb,
                       float* __restrict__ out){
    int b = blockIdx.x, tid = threadIdx.x;
    float s = 0.f;
    #pragma unroll
    for (int seg = 0; seg < 32; seg++) s += g_pool[(b*32+seg)*EMB + tid];
    float p = s * (1.f/(float)SEQ);
    float l0 = p * cw[tid*2 + 0];
    float l1 = p * cw[tid*2 + 1];
    #pragma unroll
    for (int off=16; off; off>>=1){
        l0 += __shfl_xor_sync(0xffffffffu, l0, off);
        l1 += __shfl_xor_sync(0xffffffffu, l1, off);
    }
    __shared__ float r0[8], r1[8];
    int warp = tid >> 5, lane = tid & 31;
    if (lane == 0){ r0[warp] = l0; r1[warp] = l1; }
    __syncthreads();
    if (tid == 0){
        float a = cb[0], c = cb[1];
        #pragma unroll
        for (int w = 0; w < 8; w++){ a += r0[w]; c += r1[w]; }
        out[b*2 + 0] = a; out[b*2 + 1] = c;
    }
}

// ---------------- launch ----------------
extern "C" void kernel_launch(void* const* d_in, const int* in_sizes, int n_in,
                              void* d_out, int out_size){
    const int*   tokens     = (const int*)  d_in[0];
    const float* embed      = (const float*)d_in[1];
    const float* attn_theta = (const float*)d_in[2];
    const float* combine_w  = (const float*)d_in[3];
    const float* combine_b  = (const float*)d_in[4];
    const float* ffn_theta  = (const float*)d_in[5];
    const float* lin1_w     = (const float*)d_in[6];
    const float* lin1_b     = (const float*)d_in[7];
    const float* lin2_w     = (const float*)d_in[8];
    const float* lin2_b     = (const float*)d_in[9];
    const float* ln1_g      = (const float*)d_in[10];
    const float* ln1_b      = (const float*)d_in[11];
    const float* ln2_g      = (const float*)d_in[12];
    const float* ln2_b      = (const float*)d_in[13];
    const float* cls_w      = (const float*)d_in[14];
    const float* cls_b      = (const float*)d_in[15];
    float* out = (float*)d_out;

    static int inited = 0;
    if (!inited){
        cudaFuncSetAttribute(k_attn_mma, cudaFuncAttributeMaxDynamicSharedMemorySize, SM_ATTN);
        cudaFuncSetAttribute(k_ffn_mma,  cudaFuncAttributeMaxDynamicSharedMemorySize, SM_FFN);
        inited = 1;
    }

    k_freq<<<1, 128>>>();
    {
        dim3 ga(256, 2); k_tr_attn<<<ga, 256>>>(combine_w);
        dim3 gf(512, 2); k_tr_ffn<<<gf, 256>>>(lin2_w);
    }
    k_embed<<<NROWS/4, 256>>>(tokens, embed);
    for (int l = 0; l < 2; l++){
        k_attn_mma<<<NROWS/128, 256, SM_ATTN>>>(l, attn_theta, combine_b, ln1_g, ln1_b);
        k_ffn_mma <<<NROWS/128, 256, SM_FFN >>>(l, ffn_theta, lin1_w, lin1_b, lin2_b, ln2_g, ln2_b);
    }
    k_pool<<<512, 256>>>();
    k_cls2<<<NBATCH, 256>>>(cls_w, cls_b, out);
}

// round 7
// speedup vs baseline: 3.9000x; 1.1545x over previous
#include <cuda_runtime.h>
#include <cuda_fp16.h>
#include <math.h>
#include <stdint.h>

#define NBATCH 16
#define SEQ    2048
#define EMB    256
#define NROWS  (NBATCH*SEQ)
#define FFND   512
#define XSTR   260        // Xs row stride in floats (260 mod 32 = 4 -> row bank rotation)

__device__ float  g_freq[128];
__device__ __half g_wt_attn[2*256*256];   // [f][e] transposed fp16
__device__ __half g_wt_ffn[2*256*FFND];   // [e][f] transposed fp16
__device__ float  g_pool[256*EMB];        // per-CTA column sums

// ---------------- asm helpers ----------------
__device__ __forceinline__ void mma16(float* d, const uint32_t* a, const uint32_t* b){
    asm volatile("mma.sync.aligned.m16n8k16.row.col.f32.f16.f16.f32 "
        "{%0,%1,%2,%3}, {%4,%5,%6,%7}, {%8,%9}, {%0,%1,%2,%3};"
        : "+f"(d[0]),"+f"(d[1]),"+f"(d[2]),"+f"(d[3])
        : "r"(a[0]),"r"(a[1]),"r"(a[2]),"r"(a[3]),"r"(b[0]),"r"(b[1]));
}
__device__ __forceinline__ void ldsm4(uint32_t& r0, uint32_t& r1, uint32_t& r2, uint32_t& r3,
                                      uint32_t addr){
    asm volatile("ldmatrix.sync.aligned.m8n8.x4.shared.b16 {%0,%1,%2,%3}, [%4];"
        : "=r"(r0),"=r"(r1),"=r"(r2),"=r"(r3) : "r"(addr));
}
__device__ __forceinline__ uint32_t smem_u32(const void* p){
    uint32_t a;
    asm("{ .reg .u64 t; cvta.to.shared.u64 t, %1; cvt.u32.u64 %0, t; }" : "=r"(a) : "l"(p));
    return a;
}
__device__ __forceinline__ void cpasync16(uint32_t dst, const void* src){
    asm volatile("cp.async.cg.shared.global [%0], [%1], 16;" :: "r"(dst), "l"(src));
}
__device__ __forceinline__ void cpcommit(){ asm volatile("cp.async.commit_group;" ::: "memory"); }
__device__ __forceinline__ void cpwait0(){ asm volatile("cp.async.wait_group 0;" ::: "memory"); }

// ---------------- setup kernels ----------------
__global__ void k_freq(){
    int i = threadIdx.x;
    if (i < 128) g_freq[i] = (float)exp(-(double)(2*i) * (log(10000.0) / 256.0));
}
__global__ void k_tr_attn(const float* __restrict__ W){
    int l = blockIdx.y, idx = blockIdx.x*256 + threadIdx.x;
    int e = idx & 255, f = idx >> 8;
    g_wt_attn[l*65536 + f*256 + e] = __float2half_rn(W[l*65536 + e*256 + f]);
}
__global__ void k_tr_ffn(const float* __restrict__ W2){
    int l = blockIdx.y, idx = blockIdx.x*256 + threadIdx.x;
    int f = idx & 511, e = idx >> 9;
    g_wt_ffn[l*131072 + e*512 + f] = __float2half_rn(W2[l*131072 + f*256 + e]);
}

// ---------------- smem layout (bytes) ----------------
// Xs   @0       128 x 260 f32 = 133120
// As   @133120  2 x 10240  (128 x 40 half)
// Bs   @153600  2 x 20480  (256 x 40 half)
// W1s  @194560  8 x 512 f32 = 16384
// qs   @210944  128 x 9 f32 = 4608     -> total 215552
// S sums alias As (@133120, 4KB)
#define OFF_AS  133120
#define OFF_BS  153600
#define OFF_W1  194560
#define OFF_QS  210944
#define SM_TOT  215552

// ---------------- MMA chunk: K=32 (two k16 steps), ldmatrix fragments ----------------
__device__ __forceinline__ void mma_chunk(uint32_t as_u32, uint32_t bs_u32,
                                          int wm, int wn, int lane,
                                          float acc[4][8][4]){
    int g = lane >> 3, i = lane & 7;
    // A groups: g0:(m+0..7,k0) g1:(m+8..15,k0) g2:(m+0..7,k8) g3:(m+8..15,k8)
    uint32_t abase = as_u32 + (uint32_t)((wm*64 + (g&1)*8 + i)*80 + (g>>1)*16);
    // B groups: g0:(n+0..7,k0) g1:(n+0..7,k8) g2:(n+8..15,k0) g3:(n+8..15,k8)
    uint32_t bbase = bs_u32 + (uint32_t)((wn*64 + (g>>1)*8 + i)*80 + (g&1)*16);
    #pragma unroll
    for (int ks = 0; ks < 2; ks++){
        uint32_t a[4][4], b[4][4];
        #pragma unroll
        for (int tm = 0; tm < 4; tm++)
            ldsm4(a[tm][0],a[tm][1],a[tm][2],a[tm][3], abase + tm*16*80 + ks*32);
        #pragma unroll
        for (int p = 0; p < 4; p++)
            ldsm4(b[p][0],b[p][1],b[p][2],b[p][3], bbase + p*16*80 + ks*32);
        #pragma unroll
        for (int tm = 0; tm < 4; tm++)
            #pragma unroll
            for (int p = 0; p < 4; p++){
                mma16(acc[tm][2*p],   a[tm], &b[p][0]);
                mma16(acc[tm][2*p+1], a[tm], &b[p][2]);
            }
    }
}

// ---------------- staging ----------------
__device__ __forceinline__ void stageB_async(uint32_t bs_u32, const __half* __restrict__ Wt,
                                             int rowlen, int c, int tid){
    #pragma unroll
    for (int i = 0; i < 4; i++){
        int idx = tid + 256*i;
        int seg = idx & 3, n = idx >> 2;
        cpasync16(bs_u32 + (uint32_t)(n*80 + seg*16), Wt + n*rowlen + c*32 + seg*8);
    }
}
__device__ __forceinline__ void attnA_regs(const float* __restrict__ Xs, int c, int tid,
                                           const float* __restrict__ theta, uint2* av){
    #pragma unroll
    for (int i = 0; i < 4; i++){
        int idx = tid + 256*i;
        int kk4 = (idx & 7)*4, r = idx >> 3;
        int kb = c*32 + kk4;
        float4 xv = *(const float4*)&Xs[r*XSTR + kb];
        __half2 h01 = __floats2half2_rn(__cosf(xv.x + __ldg(&theta[(kb+0)&63])),
                                        __cosf(xv.y + __ldg(&theta[(kb+1)&63])));
        __half2 h23 = __floats2half2_rn(__cosf(xv.z + __ldg(&theta[(kb+2)&63])),
                                        __cosf(xv.w + __ldg(&theta[(kb+3)&63])));
        av[i].x = *(const uint32_t*)&h01;
        av[i].y = *(const uint32_t*)&h23;
    }
}
__device__ __forceinline__ void attnA_sts(__half* __restrict__ As, int tid, const uint2* av){
    #pragma unroll
    for (int i = 0; i < 4; i++){
        int idx = tid + 256*i;
        int kk4 = (idx & 7)*4, r = idx >> 3;
        *(uint2*)&As[r*40 + kk4] = av[i];
    }
}
__device__ __forceinline__ void ffnA_stage(__half* __restrict__ As,
        const float* __restrict__ qs, const float* __restrict__ W1s,
        const float* __restrict__ b1, int c, int tid){
    int f0 = tid & 31, rg = tid >> 5;
    float wcol[8];
    #pragma unroll
    for (int n = 0; n < 8; n++) wcol[n] = W1s[n*512 + c*32 + f0];
    float bf = __ldg(&b1[c*32 + f0]);
    #pragma unroll
    for (int rr = 0; rr < 16; rr++){
        int r = rg*16 + rr;
        float a = bf;
        #pragma unroll
        for (int n = 0; n < 8; n++) a += qs[r*9 + n] * wcol[n];
        As[r*40 + f0] = __float2half_rn(fmaxf(a, 0.f));
    }
}

// ---------------- register epilogue: Xs = LN(Xs + D + bias) ----------------
__device__ __forceinline__ void epilogue(float* __restrict__ Xs, float* __restrict__ S,
        float acc[4][8][4], int wm, int wn, int gid, int tig,
        const float* __restrict__ bias, const float* __restrict__ lng,
        const float* __restrict__ lnb){
    #pragma unroll
    for (int tm = 0; tm < 4; tm++){
        int rl = wm*64 + tm*16 + gid;
        #pragma unroll
        for (int tn = 0; tn < 8; tn++){
            int col = wn*64 + tn*8 + 2*tig;
            float bx = __ldg(&bias[col]), by = __ldg(&bias[col+1]);
            float2 x0 = *(const float2*)&Xs[rl*XSTR + col];
            float2 x1 = *(const float2*)&Xs[(rl+8)*XSTR + col];
            acc[tm][tn][0] += bx + x0.x; acc[tm][tn][1] += by + x0.y;
            acc[tm][tn][2] += bx + x1.x; acc[tm][tn][3] += by + x1.y;
        }
    }
    float s[4][2], q[4][2];
    #pragma unroll
    for (int tm = 0; tm < 4; tm++){
        s[tm][0] = s[tm][1] = q[tm][0] = q[tm][1] = 0.f;
        #pragma unroll
        for (int tn = 0; tn < 8; tn++){
            s[tm][0] += acc[tm][tn][0] + acc[tm][tn][1];
            q[tm][0] += acc[tm][tn][0]*acc[tm][tn][0] + acc[tm][tn][1]*acc[tm][tn][1];
            s[tm][1] += acc[tm][tn][2] + acc[tm][tn][3];
            q[tm][1] += acc[tm][tn][2]*acc[tm][tn][2] + acc[tm][tn][3]*acc[tm][tn][3];
        }
    }
    #pragma unroll
    for (int off = 1; off <= 2; off <<= 1)
        #pragma unroll
        for (int tm = 0; tm < 4; tm++)
            #pragma unroll
            for (int h = 0; h < 2; h++){
                s[tm][h] += __shfl_xor_sync(0xffffffffu, s[tm][h], off);
                q[tm][h] += __shfl_xor_sync(0xffffffffu, q[tm][h], off);
            }
    if (tig == 0){
        #pragma unroll
        for (int tm = 0; tm < 4; tm++){
            int rl = wm*64 + tm*16 + gid;
            S[rl*8 + wn*2]        = s[tm][0];
            S[rl*8 + wn*2 + 1]    = q[tm][0];
            S[(rl+8)*8 + wn*2]    = s[tm][1];
            S[(rl+8)*8 + wn*2 +1] = q[tm][1];
        }
    }
    __syncthreads();
    float2 gv[8], bv[8];
    #pragma unroll
    for (int tn = 0; tn < 8; tn++){
        int col = wn*64 + tn*8 + 2*tig;
        gv[tn] = *(const float2*)&lng[col];
        bv[tn] = *(const float2*)&lnb[col];
    }
    #pragma unroll
    for (int tm = 0; tm < 4; tm++){
        int rl = wm*64 + tm*16 + gid;
        #pragma unroll
        for (int h = 0; h < 2; h++){
            int r = rl + 8*h;
            float Ss = S[r*8+0] + S[r*8+2] + S[r*8+4] + S[r*8+6];
            float Qq = S[r*8+1] + S[r*8+3] + S[r*8+5] + S[r*8+7];
            float m  = Ss * (1.f/256.f);
            float var = fmaxf(Qq * (1.f/256.f) - m*m, 0.f);
            float rs = rsqrtf(var + 1e-5f);
            #pragma unroll
            for (int tn = 0; tn < 8; tn++){
                int col = wn*64 + tn*8 + 2*tig;
                float z0 = acc[tm][tn][2*h], z1 = acc[tm][tn][2*h+1];
                *(float2*)&Xs[r*XSTR + col] =
                    make_float2((z0-m)*rs*gv[tn].x + bv[tn].x,
                                (z1-m)*rs*gv[tn].y + bv[tn].y);
            }
        }
    }
}

// ---------------- fused persistent kernel: 128 rows end-to-end ----------------
__global__ __launch_bounds__(256, 1) void k_fused(
    const int* __restrict__ tokens, const float* __restrict__ embed,
    const float* __restrict__ attn_theta, const float* __restrict__ combine_b,
    const float* __restrict__ ffn_theta,  const float* __restrict__ lin1_w,
    const float* __restrict__ lin1_b,     const float* __restrict__ lin2_b,
    const float* __restrict__ ln1g, const float* __restrict__ ln1b,
    const float* __restrict__ ln2g, const float* __restrict__ ln2b)
{
    extern __shared__ char sm[];
    float*  Xs  = (float*)sm;
    __half* As  = (__half*)(sm + OFF_AS);
    __half* Bs  = (__half*)(sm + OFF_BS);
    float*  W1s = (float*)(sm + OFF_W1);
    float*  qs  = (float*)(sm + OFF_QS);
    float*  S   = (float*)(sm + OFF_AS);   // alias (epilogue only)
    uint32_t as_u32 = smem_u32(As);
    uint32_t bs_u32 = smem_u32(Bs);

    int tid = threadIdx.x, lane = tid & 31, wid = tid >> 5;
    int gid = lane >> 2, tig = lane & 3;
    int wm = wid & 1, wn = wid >> 1;
    int row0 = blockIdx.x * 128;

    // ---- embed + positional encoding ----
    #pragma unroll 4
    for (int i = 0; i < 32; i++){
        int idx = tid + 256*i;
        int r = idx >> 6, c4 = (idx & 63) * 4;
        int tok = __ldg(&tokens[row0 + r]);
        float4 v = *(const float4*)&embed[tok*EMB + c4];
        float pos = (float)((row0 + r) & (SEQ-1));
        float s0,c0,s1,c1;
        sincosf(pos * g_freq[(c4>>1)+0], &s0, &c0);
        sincosf(pos * g_freq[(c4>>1)+1], &s1, &c1);
        v.x += s0; v.y += c0; v.z += s1; v.w += c1;
        *(float4*)&Xs[r*XSTR + c4] = v;
    }
    __syncthreads();

    #pragma unroll 1
    for (int l = 0; l < 2; l++){
        // ================= attention =================
        {
            const float*  theta = attn_theta + l*64;
            const __half* Wt    = g_wt_attn + l*65536;
            float acc[4][8][4];
            #pragma unroll
            for (int tm=0;tm<4;tm++)
                #pragma unroll
                for (int tn=0;tn<8;tn++)
                    #pragma unroll
                    for (int j=0;j<4;j++) acc[tm][tn][j] = 0.f;

            uint2 av[4];
            attnA_regs(Xs, 0, tid, theta, av);
            stageB_async(bs_u32, Wt, 256, 0, tid);
            cpcommit();
            attnA_sts(As, tid, av);
            cpwait0(); __syncthreads();

            for (int c = 0; c < 8; c++){
                int cur = c & 1, nxt = cur ^ 1;
                if (c + 1 < 8){
                    stageB_async(bs_u32 + nxt*20480u, Wt, 256, c+1, tid);
                    cpcommit();
                    attnA_regs(Xs, c+1, tid, theta, av);
                }
                mma_chunk(as_u32 + cur*10240u, bs_u32 + cur*20480u, wm, wn, lane, acc);
                if (c + 1 < 8){
                    attnA_sts(As + nxt*5120, tid, av);
                    cpwait0();
                }
                __syncthreads();
            }
            epilogue(Xs, S, acc, wm, wn, gid, tig,
                     combine_b + l*256, ln1g + l*256, ln1b + l*256);
            __syncthreads();
        }
        // ================= ffn =================
        {
            const float*  fth = ffn_theta + l*8;
            const float*  W1  = lin1_w + l*8*FFND;
            const float*  b1  = lin1_b + l*FFND;
            const __half* Wt2 = g_wt_ffn + l*256*FFND;
            float acc[4][8][4];
            #pragma unroll
            for (int tm=0;tm<4;tm++)
                #pragma unroll
                for (int tn=0;tn<8;tn++)
                    #pragma unroll
                    for (int j=0;j<4;j++) acc[tm][tn][j] = 0.f;

            for (int idx = tid; idx < 1024; idx += 256){
                int r = idx >> 3, n = idx & 7;
                qs[r*9 + n] = __cosf(Xs[r*XSTR + n]) * __cosf(__ldg(&fth[n]));
            }
            {
                const float4* src = (const float4*)W1;
                float4* dst = (float4*)W1s;
                #pragma unroll
                for (int i = 0; i < 4; i++) dst[tid + 256*i] = src[tid + 256*i];
            }
            stageB_async(bs_u32, Wt2, 512, 0, tid);
            cpcommit();
            __syncthreads();
            ffnA_stage(As, qs, W1s, b1, 0, tid);
            cpwait0(); __syncthreads();

            for (int c = 0; c < 16; c++){
                int cur = c & 1, nxt = cur ^ 1;
                if (c + 1 < 16){
                    stageB_async(bs_u32 + nxt*20480u, Wt2, 512, c+1, tid);
                    cpcommit();
                }
                mma_chunk(as_u32 + cur*10240u, bs_u32 + cur*20480u, wm, wn, lane, acc);
                if (c + 1 < 16){
                    ffnA_stage(As + nxt*5120, qs, W1s, b1, c+1, tid);
                    cpwait0();
                }
                __syncthreads();
            }
            epilogue(Xs, S, acc, wm, wn, gid, tig,
                     lin2_b + l*256, ln2g + l*256, ln2b + l*256);
            __syncthreads();
        }
    }

    // ---- partial pool: column sums of this CTA's 128 rows ----
    {
        float s = 0.f;
        #pragma unroll 8
        for (int r = 0; r < 128; r++) s += Xs[r*XSTR + tid];
        g_pool[blockIdx.x*256 + tid] = s;
    }
}

// ---------------- classifier ----------------
__global__ void k_cls2(const float* __restrict__ cw, const float* __restrict__ cb,
                       float* __restrict__ out){
    int b = blockIdx.x, tid = threadIdx.x;
    float s = 0.f;
    #pragma unroll
    for (int seg = 0; seg < 16; seg++) s += g_pool[(b*16+seg)*256 + tid];
    float p = s * (1.f/(float)SEQ);
    float l0 = p * cw[tid*2 + 0];
    float l1 = p * cw[tid*2 + 1];
    #pragma unroll
    for (int off=16; off; off>>=1){
        l0 += __shfl_xor_sync(0xffffffffu, l0, off);
        l1 += __shfl_xor_sync(0xffffffffu, l1, off);
    }
    __shared__ float r0[8], r1[8];
    int warp = tid >> 5, lane = tid & 31;
    if (lane == 0){ r0[warp] = l0; r1[warp] = l1; }
    __syncthreads();
    if (tid == 0){
        float a = cb[0], c = cb[1];
        #pragma unroll
        for (int w = 0; w < 8; w++){ a += r0[w]; c += r1[w]; }
        out[b*2 + 0] = a; out[b*2 + 1] = c;
    }
}

// ---------------- launch ----------------
extern "C" void kernel_launch(void* const* d_in, const int* in_sizes, int n_in,
                              void* d_out, int out_size){
    const int*   tokens     = (const int*)  d_in[0];
    const float* embed      = (const float*)d_in[1];
    const float* attn_theta = (const float*)d_in[2];
    const float* combine_w  = (const float*)d_in[3];
    const float* combine_b  = (const float*)d_in[4];
    const float* ffn_theta  = (const float*)d_in[5];
    const float* lin1_w     = (const float*)d_in[6];
    const float* lin1_b     = (const float*)d_in[7];
    const float* lin2_w     = (const float*)d_in[8];
    const float* lin2_b     = (const float*)d_in[9];
    const float* ln1_g      = (const float*)d_in[10];
    const float* ln1_b      = (const float*)d_in[11];
    const float* ln2_g      = (const float*)d_in[12];
    const float* ln2_b      = (const float*)d_in[13];
    const float* cls_w      = (const float*)d_in[14];
    const float* cls_b      = (const float*)d_in[15];
    float* out = (float*)d_out;

    static int inited = 0;
    if (!inited){
        cudaFuncSetAttribute(k_fused, cudaFuncAttributeMaxDynamicSharedMemorySize, SM_TOT);
        inited = 1;
    }

    k_freq<<<1, 128>>>();
    {
        dim3 ga(256, 2); k_tr_attn<<<ga, 256>>>(combine_w);
        dim3 gf(512, 2); k_tr_ffn<<<gf, 256>>>(lin2_w);
    }
    k_fused<<<NROWS/128, 256, SM_TOT>>>(tokens, embed,
        attn_theta, combine_b, ffn_theta, lin1_w, lin1_b, lin2_b,
        ln1_g, ln1_b, ln2_g, ln2_b);
    k_cls2<<<NBATCH, 256>>>(cls_w, cls_b, out);
}

// round 8
// speedup vs baseline: 4.6511x; 1.1926x over previous
#include <cuda_runtime.h>
#include <cuda_fp16.h>
#include <math.h>
#include <stdint.h>

#define NBATCH 16
#define SEQ    2048
#define EMB    256
#define NROWS  (NBATCH*SEQ)
#define FFND   512
#define XSTR   260

__device__ float  g_freq[128];
__device__ __half g_wt_attn[2*256*256];
__device__ __half g_wt_ffn[2*256*FFND];
__device__ float  g_pool[256*EMB];

// ---------------- asm helpers ----------------
__device__ __forceinline__ void mma16(float* d, const uint32_t* a, const uint32_t* b){
    asm volatile("mma.sync.aligned.m16n8k16.row.col.f32.f16.f16.f32 "
        "{%0,%1,%2,%3}, {%4,%5,%6,%7}, {%8,%9}, {%0,%1,%2,%3};"
        : "+f"(d[0]),"+f"(d[1]),"+f"(d[2]),"+f"(d[3])
        : "r"(a[0]),"r"(a[1]),"r"(a[2]),"r"(a[3]),"r"(b[0]),"r"(b[1]));
}
__device__ __forceinline__ void ldsm4(uint32_t& r0, uint32_t& r1, uint32_t& r2, uint32_t& r3,
                                      uint32_t addr){
    asm volatile("ldmatrix.sync.aligned.m8n8.x4.shared.b16 {%0,%1,%2,%3}, [%4];"
        : "=r"(r0),"=r"(r1),"=r"(r2),"=r"(r3) : "r"(addr));
}
__device__ __forceinline__ uint32_t smem_u32(const void* p){
    uint32_t a;
    asm("{ .reg .u64 t; cvta.to.shared.u64 t, %1; cvt.u32.u64 %0, t; }" : "=r"(a) : "l"(p));
    return a;
}
__device__ __forceinline__ void cpasync16(uint32_t dst, const void* src){
    asm volatile("cp.async.cg.shared.global [%0], [%1], 16;" :: "r"(dst), "l"(src));
}
__device__ __forceinline__ void cpcommit(){ asm volatile("cp.async.commit_group;" ::: "memory"); }
__device__ __forceinline__ void cpwait0(){ asm volatile("cp.async.wait_group 0;" ::: "memory"); }

// ---------------- setup kernels ----------------
__global__ void k_freq(){
    int i = threadIdx.x;
    if (i < 128) g_freq[i] = (float)exp(-(double)(2*i) * (log(10000.0) / 256.0));
}
__global__ void k_tr_attn(const float* __restrict__ W){
    int l = blockIdx.y, idx = blockIdx.x*256 + threadIdx.x;
    int e = idx & 255, f = idx >> 8;
    g_wt_attn[l*65536 + f*256 + e] = __float2half_rn(W[l*65536 + e*256 + f]);
}
__global__ void k_tr_ffn(const float* __restrict__ W2){
    int l = blockIdx.y, idx = blockIdx.x*256 + threadIdx.x;
    int f = idx & 511, e = idx >> 9;
    g_wt_ffn[l*131072 + e*512 + f] = __float2half_rn(W2[l*131072 + f*256 + e]);
}

// ---------------- smem layout (bytes) ----------------
#define OFF_AS  133120
#define OFF_BS  153600
#define OFF_W1  194560
#define OFF_QS  210944
#define SM_TOT  215552

// ---------------- MMA chunk: warp tile 32x64, K=32 ----------------
__device__ __forceinline__ void mma_chunk(uint32_t as_u32, uint32_t bs_u32,
                                          int wm, int wn, int lane,
                                          float acc[2][8][4]){
    int g = lane >> 3, i = lane & 7;
    uint32_t abase = as_u32 + (uint32_t)((wm*32 + (g&1)*8 + i)*80 + (g>>1)*16);
    uint32_t bbase = bs_u32 + (uint32_t)((wn*64 + (g>>1)*8 + i)*80 + (g&1)*16);
    #pragma unroll
    for (int ks = 0; ks < 2; ks++){
        uint32_t a[2][4], b[4][4];
        #pragma unroll
        for (int tm = 0; tm < 2; tm++)
            ldsm4(a[tm][0],a[tm][1],a[tm][2],a[tm][3], abase + tm*16*80 + ks*32);
        #pragma unroll
        for (int p = 0; p < 4; p++)
            ldsm4(b[p][0],b[p][1],b[p][2],b[p][3], bbase + p*16*80 + ks*32);
        #pragma unroll
        for (int tm = 0; tm < 2; tm++)
            #pragma unroll
            for (int p = 0; p < 4; p++){
                mma16(acc[tm][2*p],   a[tm], &b[p][0]);
                mma16(acc[tm][2*p+1], a[tm], &b[p][2]);
            }
    }
}

// ---------------- staging (512 threads) ----------------
__device__ __forceinline__ void stageB_async(uint32_t bs_u32, const __half* __restrict__ Wt,
                                             int rowlen, int c, int tid){
    #pragma unroll
    for (int i = 0; i < 2; i++){
        int idx = tid + 512*i;
        int seg = idx & 3, n = idx >> 2;
        cpasync16(bs_u32 + (uint32_t)(n*80 + seg*16), Wt + n*rowlen + c*32 + seg*8);
    }
}
__device__ __forceinline__ void attnA_regs(const float* __restrict__ Xs, int c, int tid,
                                           const float* __restrict__ theta, uint2* av){
    #pragma unroll
    for (int i = 0; i < 2; i++){
        int idx = tid + 512*i;
        int kk4 = (idx & 7)*4, r = idx >> 3;
        int kb = c*32 + kk4;
        float4 xv = *(const float4*)&Xs[r*XSTR + kb];
        __half2 h01 = __floats2half2_rn(__cosf(xv.x + __ldg(&theta[(kb+0)&63])),
                                        __cosf(xv.y + __ldg(&theta[(kb+1)&63])));
        __half2 h23 = __floats2half2_rn(__cosf(xv.z + __ldg(&theta[(kb+2)&63])),
                                        __cosf(xv.w + __ldg(&theta[(kb+3)&63])));
        av[i].x = *(const uint32_t*)&h01;
        av[i].y = *(const uint32_t*)&h23;
    }
}
__device__ __forceinline__ void attnA_sts(__half* __restrict__ As, int tid, const uint2* av){
    #pragma unroll
    for (int i = 0; i < 2; i++){
        int idx = tid + 512*i;
        int kk4 = (idx & 7)*4, r = idx >> 3;
        *(uint2*)&As[r*40 + kk4] = av[i];
    }
}
__device__ __forceinline__ void ffnA_stage(__half* __restrict__ As,
        const float* __restrict__ qs, const float* __restrict__ W1s,
        const float* __restrict__ b1, int c, int tid){
    int f0 = tid & 31, rg = tid >> 5;   // 16 row groups of 8
    float wcol[8];
    #pragma unroll
    for (int n = 0; n < 8; n++) wcol[n] = W1s[n*512 + c*32 + f0];
    float bf = __ldg(&b1[c*32 + f0]);
    #pragma unroll
    for (int rr = 0; rr < 8; rr++){
        int r = rg*8 + rr;
        float a = bf;
        #pragma unroll
        for (int n = 0; n < 8; n++) a += qs[r*9 + n] * wcol[n];
        As[r*40 + f0] = __float2half_rn(fmaxf(a, 0.f));
    }
}

// ---------------- register epilogue: Xs = LN(Xs + D + bias) ----------------
__device__ __forceinline__ void epilogue(float* __restrict__ Xs, float* __restrict__ S,
        float acc[2][8][4], int wm, int wn, int gid, int tig,
        const float* __restrict__ bias, const float* __restrict__ lng,
        const float* __restrict__ lnb){
    #pragma unroll
    for (int tm = 0; tm < 2; tm++){
        int rl = wm*32 + tm*16 + gid;
        #pragma unroll
        for (int tn = 0; tn < 8; tn++){
            int col = wn*64 + tn*8 + 2*tig;
            float bx = __ldg(&bias[col]), by = __ldg(&bias[col+1]);
            float2 x0 = *(const float2*)&Xs[rl*XSTR + col];
            float2 x1 = *(const float2*)&Xs[(rl+8)*XSTR + col];
            acc[tm][tn][0] += bx + x0.x; acc[tm][tn][1] += by + x0.y;
            acc[tm][tn][2] += bx + x1.x; acc[tm][tn][3] += by + x1.y;
        }
    }
    float s[2][2], q[2][2];
    #pragma unroll
    for (int tm = 0; tm < 2; tm++){
        s[tm][0] = s[tm][1] = q[tm][0] = q[tm][1] = 0.f;
        #pragma unroll
        for (int tn = 0; tn < 8; tn++){
            s[tm][0] += acc[tm][tn][0] + acc[tm][tn][1];
            q[tm][0] += acc[tm][tn][0]*acc[tm][tn][0] + acc[tm][tn][1]*acc[tm][tn][1];
            s[tm][1] += acc[tm][tn][2] + acc[tm][tn][3];
            q[tm][1] += acc[tm][tn][2]*acc[tm][tn][2] + acc[tm][tn][3]*acc[tm][tn][3];
        }
    }
    #pragma unroll
    for (int off = 1; off <= 2; off <<= 1)
        #pragma unroll
        for (int tm = 0; tm < 2; tm++)
            #pragma unroll
            for (int h = 0; h < 2; h++){
                s[tm][h] += __shfl_xor_sync(0xffffffffu, s[tm][h], off);
                q[tm][h] += __shfl_xor_sync(0xffffffffu, q[tm][h], off);
            }
    if (tig == 0){
        #pragma unroll
        for (int tm = 0; tm < 2; tm++){
            int rl = wm*32 + tm*16 + gid;
            S[rl*8 + wn*2]        = s[tm][0];
            S[rl*8 + wn*2 + 1]    = q[tm][0];
            S[(rl+8)*8 + wn*2]    = s[tm][1];
            S[(rl+8)*8 + wn*2 +1] = q[tm][1];
        }
    }
    __syncthreads();
    float2 gv[8], bv[8];
    #pragma unroll
    for (int tn = 0; tn < 8; tn++){
        int col = wn*64 + tn*8 + 2*tig;
        gv[tn] = *(const float2*)&lng[col];
        bv[tn] = *(const float2*)&lnb[col];
    }
    #pragma unroll
    for (int tm = 0; tm < 2; tm++){
        int rl = wm*32 + tm*16 + gid;
        #pragma unroll
        for (int h = 0; h < 2; h++){
            int r = rl + 8*h;
            float Ss = S[r*8+0] + S[r*8+2] + S[r*8+4] + S[r*8+6];
            float Qq = S[r*8+1] + S[r*8+3] + S[r*8+5] + S[r*8+7];
            float m  = Ss * (1.f/256.f);
            float var = fmaxf(Qq * (1.f/256.f) - m*m, 0.f);
            float rs = rsqrtf(var + 1e-5f);
            #pragma unroll
            for (int tn = 0; tn < 8; tn++){
                int col = wn*64 + tn*8 + 2*tig;
                float z0 = acc[tm][tn][2*h], z1 = acc[tm][tn][2*h+1];
                *(float2*)&Xs[r*XSTR + col] =
                    make_float2((z0-m)*rs*gv[tn].x + bv[tn].x,
                                (z1-m)*rs*gv[tn].y + bv[tn].y);
            }
        }
    }
}

// ---------------- fused persistent kernel ----------------
__global__ __launch_bounds__(512, 1) void k_fused(
    const int* __restrict__ tokens, const float* __restrict__ embed,
    const float* __restrict__ attn_theta, const float* __restrict__ combine_b,
    const float* __restrict__ ffn_theta,  const float* __restrict__ lin1_w,
    const float* __restrict__ lin1_b,     const float* __restrict__ lin2_b,
    const float* __restrict__ ln1g, const float* __restrict__ ln1b,
    const float* __restrict__ ln2g, const float* __restrict__ ln2b)
{
    extern __shared__ char sm[];
    float*  Xs  = (float*)sm;
    __half* As  = (__half*)(sm + OFF_AS);
    __half* Bs  = (__half*)(sm + OFF_BS);
    float*  W1s = (float*)(sm + OFF_W1);
    float*  qs  = (float*)(sm + OFF_QS);
    float*  S   = (float*)(sm + OFF_AS);   // alias (epilogue only)
    uint32_t as_u32 = smem_u32(As);
    uint32_t bs_u32 = smem_u32(Bs);

    int tid = threadIdx.x, lane = tid & 31, wid = tid >> 5;
    int gid = lane >> 2, tig = lane & 3;
    int wm = wid & 3, wn = wid >> 2;   // 4 x 4 warp grid: 32-row x 64-col tiles
    int row0 = blockIdx.x * 128;

    // ---- embed + positional encoding ----
    #pragma unroll 4
    for (int i = 0; i < 16; i++){
        int idx = tid + 512*i;
        int r = idx >> 6, c4 = (idx & 63) * 4;
        int tok = __ldg(&tokens[row0 + r]);
        float4 v = *(const float4*)&embed[tok*EMB + c4];
        float pos = (float)((row0 + r) & (SEQ-1));
        float s0,c0,s1,c1;
        sincosf(pos * g_freq[(c4>>1)+0], &s0, &c0);
        sincosf(pos * g_freq[(c4>>1)+1], &s1, &c1);
        v.x += s0; v.y += c0; v.z += s1; v.w += c1;
        *(float4*)&Xs[r*XSTR + c4] = v;
    }
    __syncthreads();

    #pragma unroll 1
    for (int l = 0; l < 2; l++){
        // ================= attention =================
        {
            const float*  theta = attn_theta + l*64;
            const __half* Wt    = g_wt_attn + l*65536;
            float acc[2][8][4];
            #pragma unroll
            for (int tm=0;tm<2;tm++)
                #pragma unroll
                for (int tn=0;tn<8;tn++)
                    #pragma unroll
                    for (int j=0;j<4;j++) acc[tm][tn][j] = 0.f;

            uint2 av[2];
            attnA_regs(Xs, 0, tid, theta, av);
            stageB_async(bs_u32, Wt, 256, 0, tid);
            cpcommit();
            attnA_sts(As, tid, av);
            cpwait0(); __syncthreads();

            for (int c = 0; c < 8; c++){
                int cur = c & 1, nxt = cur ^ 1;
                if (c + 1 < 8){
                    stageB_async(bs_u32 + nxt*20480u, Wt, 256, c+1, tid);
                    cpcommit();
                    attnA_regs(Xs, c+1, tid, theta, av);
                }
                mma_chunk(as_u32 + cur*10240u, bs_u32 + cur*20480u, wm, wn, lane, acc);
                if (c + 1 < 8){
                    attnA_sts(As + nxt*5120, tid, av);
                    cpwait0();
                }
                __syncthreads();
            }
            epilogue(Xs, S, acc, wm, wn, gid, tig,
                     combine_b + l*256, ln1g + l*256, ln1b + l*256);
            __syncthreads();
        }
        // ================= ffn =================
        {
            const float*  fth = ffn_theta + l*8;
            const float*  W1  = lin1_w + l*8*FFND;
            const float*  b1  = lin1_b + l*FFND;
            const __half* Wt2 = g_wt_ffn + l*256*FFND;
            float acc[2][8][4];
            #pragma unroll
            for (int tm=0;tm<2;tm++)
                #pragma unroll
                for (int tn=0;tn<8;tn++)
                    #pragma unroll
                    for (int j=0;j<4;j++) acc[tm][tn][j] = 0.f;

            for (int idx = tid; idx < 1024; idx += 512){
                int r = idx >> 3, n = idx & 7;
                qs[r*9 + n] = __cosf(Xs[r*XSTR + n]) * __cosf(__ldg(&fth[n]));
            }
            {
                const float4* src = (const float4*)W1;
                float4* dst = (float4*)W1s;
                #pragma unroll
                for (int i = 0; i < 2; i++) dst[tid + 512*i] = src[tid + 512*i];
            }
            stageB_async(bs_u32, Wt2, 512, 0, tid);
            cpcommit();
            __syncthreads();
            ffnA_stage(As, qs, W1s, b1, 0, tid);
            cpwait0(); __syncthreads();

            for (int c = 0; c < 16; c++){
                int cur = c & 1, nxt = cur ^ 1;
                if (c + 1 < 16){
                    stageB_async(bs_u32 + nxt*20480u, Wt2, 512, c+1, tid);
                    cpcommit();
                }
                mma_chunk(as_u32 + cur*10240u, bs_u32 + cur*20480u, wm, wn, lane, acc);
                if (c + 1 < 16){
                    ffnA_stage(As + nxt*5120, qs, W1s, b1, c+1, tid);
                    cpwait0();
                }
                __syncthreads();
            }
            epilogue(Xs, S, acc, wm, wn, gid, tig,
                     lin2_b + l*256, ln2g + l*256, ln2b + l*256);
            __syncthreads();
        }
    }

    // ---- partial pool: column sums over 128 rows, split across 2 half-row groups ----
    {
        int col = tid & 255, half = tid >> 8;
        float s = 0.f;
        #pragma unroll 8
        for (int r = half*64; r < half*64 + 64; r++) s += Xs[r*XSTR + col];
        float* P = (float*)(sm + OFF_AS);
        P[half*256 + col] = s;
        __syncthreads();
        if (tid < 256)
            g_pool[blockIdx.x*256 + tid] = P[tid] + P[256 + tid];
    }
}

// ---------------- classifier ----------------
__global__ void k_cls2(const float* __restrict__ cw, const float* __restrict__ cb,
                       float* __restrict__ out){
    int b = blockIdx.x, tid = threadIdx.x;
    float s = 0.f;
    #pragma unroll
    for (int seg = 0; seg < 16; seg++) s += g_pool[(b*16+seg)*256 + tid];
    float p = s * (1.f/(float)SEQ);
    float l0 = p * cw[tid*2 + 0];
    float l1 = p * cw[tid*2 + 1];
    #pragma unroll
    for (int off=16; off; off>>=1){
        l0 += __shfl_xor_sync(0xffffffffu, l0, off);
        l1 += __shfl_xor_sync(0xffffffffu, l1, off);
    }
    __shared__ float r0[8], r1[8];
    int warp = tid >> 5, lane = tid & 31;
    if (lane == 0){ r0[warp] = l0; r1[warp] = l1; }
    __syncthreads();
    if (tid == 0){
        float a = cb[0], c = cb[1];
        #pragma unroll
        for (int w = 0; w < 8; w++){ a += r0[w]; c += r1[w]; }
        out[b*2 + 0] = a; out[b*2 + 1] = c;
    }
}

// ---------------- launch ----------------
extern "C" void kernel_launch(void* const* d_in, const int* in_sizes, int n_in,
                              void* d_out, int out_size){
    const int*   tokens     = (const int*)  d_in[0];
    const float* embed      = (const float*)d_in[1];
    const float* attn_theta = (const float*)d_in[2];
    const float* combine_w  = (const float*)d_in[3];
    const float* combine_b  = (const float*)d_in[4];
    const float* ffn_theta  = (const float*)d_in[5];
    const float* lin1_w     = (const float*)d_in[6];
    const float* lin1_b     = (const float*)d_in[7];
    const float* lin2_w     = (const float*)d_in[8];
    const float* lin2_b     = (const float*)d_in[9];
    const float* ln1_g      = (const float*)d_in[10];
    const float* ln1_b      = (const float*)d_in[11];
    const float* ln2_g      = (const float*)d_in[12];
    const float* ln2_b      = (const float*)d_in[13];
    const float* cls_w      = (const float*)d_in[14];
    const float* cls_b      = (const float*)d_in[15];
    float* out = (float*)d_out;

    static int inited = 0;
    if (!inited){
        cudaFuncSetAttribute(k_fused, cudaFuncAttributeMaxDynamicSharedMemorySize, SM_TOT);
        inited = 1;
    }

    k_freq<<<1, 128>>>();
    {
        dim3 ga(256, 2); k_tr_attn<<<ga, 256>>>(combine_w);
        dim3 gf(512, 2); k_tr_ffn<<<gf, 256>>>(lin2_w);
    }
    k_fused<<<NROWS/128, 512, SM_TOT>>>(tokens, embed,
        attn_theta, combine_b, ffn_theta, lin1_w, lin1_b, lin2_b,
        ln1_g, ln1_b, ln2_g, ln2_b);
    k_cls2<<<NBATCH, 256>>>(cls_w, cls_b, out);
}